// round 5
// baseline (speedup 1.0000x reference)
#include <cuda_runtime.h>
#include <math.h>
#include <stdint.h>

// ---------------- problem constants ----------------
#define B_   32768
#define T_   7
#define EIN  60
#define DIN  36
#define U_   356
#define G_   1424          // 4*U
#define H1_  768
#define OUT_ 168
#define KE_  (U_ + EIN)    // 416 fused K (encoder)
#define KD_  (U_ + DIN)    // 392 fused K (decoder)

// ---------------- scratch (device globals; total < 2 GB) -------------------
__device__ __align__(16) float g_h0  [(size_t)B_ * U_];
__device__ __align__(16) float g_h1  [(size_t)B_ * U_];
__device__ __align__(16) float g_c   [(size_t)B_ * U_];
__device__ __align__(16) float g_dec [(size_t)B_ * T_ * U_]; // 327 MB
__device__ __align__(16) float g_b1  [(size_t)B_ * H1_];
__device__ __align__(16) float g_b2  [(size_t)B_ * H1_];
// fused gate-interleaved recurrent weights, K-major [1424, K]
__device__ __align__(16) float g_wfe [G_ * KE_];
__device__ __align__(16) float g_wfd [G_ * KD_];
__device__ __align__(16) float g_bpe [G_];
__device__ __align__(16) float g_bpd [G_];
// transposed head weights (K-major [N,K])
#define WT_MAP  0                         // [768,2492]
#define WT_W1   (WT_MAP + 768*2492)       // [768,768]
#define WT_W2   (WT_W1  + 768*768)        // [768,768]
#define WT_WO   (WT_W2  + 768*768)        // [168,768]
#define WT_TOTAL (WT_WO + 168*768)
__device__ __align__(16) float g_wT[WT_TOTAL];

// ==================== tf32 helpers ====================
__device__ __forceinline__ uint32_t f2tf32(float f) {
    uint32_t u;
    asm("cvt.rna.tf32.f32 %0, %1;" : "=r"(u) : "f"(f));
    return u;
}

__device__ __forceinline__ void mma_tf32(float c[4],
                                         uint32_t a0, uint32_t a1,
                                         uint32_t a2, uint32_t a3,
                                         uint32_t b0, uint32_t b1)
{
    asm volatile(
        "mma.sync.aligned.m16n8k8.row.col.f32.tf32.tf32.f32 "
        "{%0,%1,%2,%3}, {%4,%5,%6,%7}, {%8,%9}, {%0,%1,%2,%3};"
        : "+f"(c[0]), "+f"(c[1]), "+f"(c[2]), "+f"(c[3])
        : "r"(a0), "r"(a1), "r"(a2), "r"(a3), "r"(b0), "r"(b1));
}

__device__ __forceinline__ float sigmoidf_(float v) {
    return 1.f / (1.f + expf(-v));
}

#define SSTRIDE 20   // smem row stride in words (conflict-free quad pattern)

// ==================== fused LSTM step ====================
// One tf32 GEMM over concatenated K = [h | x_t] @ Wf (gate-interleaved,
// K-major [1424, K]) with the LSTM cell in the epilogue.
// 128x128 tile, BK=16, 256 threads (8 warps 2x4, each 64x32).
// hin/hout ping-pong; c in place (block-exclusive elements); dec optional.
template<int WRITE_DEC>
__global__ void __launch_bounds__(256)
lstm_step(const float* __restrict__ hin,
          const float* __restrict__ xin, int ldx, int Kx,
          const float* __restrict__ Wf,
          const float* __restrict__ bperm,
          float* __restrict__ hout, float* __restrict__ cst,
          float* __restrict__ dec, int dec_off)
{
    __shared__ __align__(16) char sraw[40960];
    uint32_t* Ab = (uint32_t*)sraw;             // [2][128*SSTRIDE]
    uint32_t* Bb = (uint32_t*)(sraw + 20480);   // [2][128*SSTRIDE]
    float*    zs = (float*)sraw;                // epilogue overlay: 64*132 fl

    const int K  = U_ + Kx;
    const int tid  = threadIdx.x;
    const int lane = tid & 31;
    const int w    = tid >> 5;
    const int m0   = blockIdx.y * 128;
    const int n0   = blockIdx.x * 128;

    const int wm = (w >> 2) * 64;
    const int wn = (w & 3) * 32;
    const int g  = lane >> 2;
    const int q4 = lane & 3;

    const int r0s = tid >> 2;
    const int k0s = (tid & 3) * 4;
    const int r1s = r0s + 64;

    float acc[4][4][4];
#pragma unroll
    for (int i = 0; i < 4; i++)
#pragma unroll
        for (int j = 0; j < 4; j++)
#pragma unroll
            for (int q = 0; q < 4; q++) acc[i][j][q] = 0.f;

    const int nck = (K + 15) >> 4;

    float4 pa0, pa1, pb0, pb1;
    auto loadA4 = [&](int r, int k) -> float4 {
        if (k < U_)
            return *reinterpret_cast<const float4*>(
                       &hin[(size_t)(m0 + r) * U_ + k]);
        if (k < K)
            return *reinterpret_cast<const float4*>(
                       &xin[(size_t)(m0 + r) * ldx + (k - U_)]);
        return make_float4(0.f, 0.f, 0.f, 0.f);
    };
    auto gload = [&](int c) {
        const int k = c * 16 + k0s;
        pa0 = loadA4(r0s, k);
        pa1 = loadA4(r1s, k);
        const int n_0 = n0 + r0s, n_1 = n0 + r1s;
        pb0 = (k < K && n_0 < G_) ? *reinterpret_cast<const float4*>(
                                        &Wf[(size_t)n_0 * K + k])
                                  : make_float4(0.f, 0.f, 0.f, 0.f);
        pb1 = (k < K && n_1 < G_) ? *reinterpret_cast<const float4*>(
                                        &Wf[(size_t)n_1 * K + k])
                                  : make_float4(0.f, 0.f, 0.f, 0.f);
    };
    auto sstore = [&](int s) {
        uint32_t* a = &Ab[s * 128 * SSTRIDE + r0s * SSTRIDE + k0s];
        a[0] = f2tf32(pa0.x); a[1] = f2tf32(pa0.y);
        a[2] = f2tf32(pa0.z); a[3] = f2tf32(pa0.w);
        a = &Ab[s * 128 * SSTRIDE + r1s * SSTRIDE + k0s];
        a[0] = f2tf32(pa1.x); a[1] = f2tf32(pa1.y);
        a[2] = f2tf32(pa1.z); a[3] = f2tf32(pa1.w);
        uint32_t* b = &Bb[s * 128 * SSTRIDE + r0s * SSTRIDE + k0s];
        b[0] = f2tf32(pb0.x); b[1] = f2tf32(pb0.y);
        b[2] = f2tf32(pb0.z); b[3] = f2tf32(pb0.w);
        b = &Bb[s * 128 * SSTRIDE + r1s * SSTRIDE + k0s];
        b[0] = f2tf32(pb1.x); b[1] = f2tf32(pb1.y);
        b[2] = f2tf32(pb1.z); b[3] = f2tf32(pb1.w);
    };

    gload(0);
    sstore(0);
    __syncthreads();

    for (int c = 0; c < nck; c++) {
        const int cur = c & 1;
        if (c + 1 < nck) gload(c + 1);
#pragma unroll
        for (int kg = 0; kg < 2; kg++) {
            const int kb = kg * 8;
            uint32_t af[4][4], bf[4][2];
#pragma unroll
            for (int mt = 0; mt < 4; mt++) {
                const uint32_t* ar =
                    &Ab[cur * 128 * SSTRIDE + (wm + mt * 16 + g) * SSTRIDE + kb + q4];
                af[mt][0] = ar[0];
                af[mt][1] = ar[8 * SSTRIDE];
                af[mt][2] = ar[4];
                af[mt][3] = ar[8 * SSTRIDE + 4];
            }
#pragma unroll
            for (int nt = 0; nt < 4; nt++) {
                const uint32_t* br =
                    &Bb[cur * 128 * SSTRIDE + (wn + nt * 8 + g) * SSTRIDE + kb + q4];
                bf[nt][0] = br[0];
                bf[nt][1] = br[4];
            }
#pragma unroll
            for (int mt = 0; mt < 4; mt++)
#pragma unroll
                for (int nt = 0; nt < 4; nt++)
                    mma_tf32(acc[mt][nt],
                             af[mt][0], af[mt][1], af[mt][2], af[mt][3],
                             bf[nt][0], bf[nt][1]);
        }
        if (c + 1 < nck) sstore((c + 1) & 1);
        __syncthreads();
    }

    // ---- epilogue: z -> smem (64-row halves) -> LSTM cell ----
    const int ubase = n0 >> 2;      // first unit of this tile
#pragma unroll
    for (int half = 0; half < 2; half++) {
        if ((w >> 2) == half) {
#pragma unroll
            for (int mt = 0; mt < 4; mt++) {
#pragma unroll
                for (int nt = 0; nt < 4; nt++) {
                    const int col = n0 + wn + nt * 8 + 2 * q4;
                    if (col >= G_) continue;
                    const float bx = bperm[col], by = bperm[col + 1];
                    const int cr = wn + nt * 8 + 2 * q4;
                    const int rl = mt * 16 + g;
                    zs[rl * 132 + cr]           = acc[mt][nt][0] + bx;
                    zs[rl * 132 + cr + 1]       = acc[mt][nt][1] + by;
                    zs[(rl + 8) * 132 + cr]     = acc[mt][nt][2] + bx;
                    zs[(rl + 8) * 132 + cr + 1] = acc[mt][nt][3] + by;
                }
            }
        }
        __syncthreads();
        for (int i = tid; i < 64 * 32; i += 256) {
            const int rl = i & 63;
            const int ul = i >> 6;
            const int unit = ubase + ul;
            if (unit < U_) {
                const int b = m0 + half * 64 + rl;
                const float4 zv =
                    *reinterpret_cast<const float4*>(&zs[rl * 132 + ul * 4]);
                const float iv = sigmoidf_(zv.x);
                const float fv = sigmoidf_(zv.y);
                const float gv = tanhf(zv.z);
                const float ov = sigmoidf_(zv.w);
                const size_t ci = (size_t)b * U_ + unit;
                const float cn = fv * cst[ci] + iv * gv;
                const float hn = ov * tanhf(cn);
                cst[ci] = cn;
                hout[ci] = hn;
                if (WRITE_DEC)
                    dec[(size_t)b * (T_ * U_) + dec_off + unit] = hn;
            }
        }
        __syncthreads();
    }
}

// ==================== tf32 mma.sync GEMM (head) ====================
template<int ACT> // 0 none, 1 relu, 2 tanh
__global__ void __launch_bounds__(256)
tf32_gemm(const float* __restrict__ A, int lda,
          const float* __restrict__ Bt, int ldb,
          float* __restrict__ C, int ldc,
          const float* __restrict__ bias,
          int M, int N, int K)
{
    __shared__ uint32_t As[2][128 * SSTRIDE];
    __shared__ uint32_t Bs[2][128 * SSTRIDE];

    const int tid  = threadIdx.x;
    const int lane = tid & 31;
    const int w    = tid >> 5;
    const int m0   = blockIdx.y * 128;
    const int n0   = blockIdx.x * 128;

    const int wm = (w >> 2) * 64;
    const int wn = (w & 3) * 32;
    const int g  = lane >> 2;
    const int q4 = lane & 3;

    const int r0s = tid >> 2;
    const int k0s = (tid & 3) * 4;
    const int r1s = r0s + 64;

    float acc[4][4][4];
#pragma unroll
    for (int i = 0; i < 4; i++)
#pragma unroll
        for (int j = 0; j < 4; j++)
#pragma unroll
            for (int q = 0; q < 4; q++) acc[i][j][q] = 0.f;

    const int nck = (K + 15) >> 4;

    float4 pa0, pa1, pb0, pb1;
    auto gload = [&](int c) {
        const int k = c * 16 + k0s;
        pa0 = (k < K) ? *reinterpret_cast<const float4*>(
                            &A[(size_t)(m0 + r0s) * lda + k])
                      : make_float4(0.f, 0.f, 0.f, 0.f);
        pa1 = (k < K) ? *reinterpret_cast<const float4*>(
                            &A[(size_t)(m0 + r1s) * lda + k])
                      : make_float4(0.f, 0.f, 0.f, 0.f);
        const int n_0 = n0 + r0s, n_1 = n0 + r1s;
        pb0 = (k < K && n_0 < N) ? *reinterpret_cast<const float4*>(
                                       &Bt[(size_t)n_0 * ldb + k])
                                 : make_float4(0.f, 0.f, 0.f, 0.f);
        pb1 = (k < K && n_1 < N) ? *reinterpret_cast<const float4*>(
                                       &Bt[(size_t)n_1 * ldb + k])
                                 : make_float4(0.f, 0.f, 0.f, 0.f);
    };
    auto sstore = [&](int s) {
        uint32_t* a = &As[s][r0s * SSTRIDE + k0s];
        a[0] = f2tf32(pa0.x); a[1] = f2tf32(pa0.y);
        a[2] = f2tf32(pa0.z); a[3] = f2tf32(pa0.w);
        a = &As[s][r1s * SSTRIDE + k0s];
        a[0] = f2tf32(pa1.x); a[1] = f2tf32(pa1.y);
        a[2] = f2tf32(pa1.z); a[3] = f2tf32(pa1.w);
        uint32_t* b = &Bs[s][r0s * SSTRIDE + k0s];
        b[0] = f2tf32(pb0.x); b[1] = f2tf32(pb0.y);
        b[2] = f2tf32(pb0.z); b[3] = f2tf32(pb0.w);
        b = &Bs[s][r1s * SSTRIDE + k0s];
        b[0] = f2tf32(pb1.x); b[1] = f2tf32(pb1.y);
        b[2] = f2tf32(pb1.z); b[3] = f2tf32(pb1.w);
    };

    gload(0);
    sstore(0);
    __syncthreads();

    for (int c = 0; c < nck; c++) {
        const int cur = c & 1;
        if (c + 1 < nck) gload(c + 1);
#pragma unroll
        for (int kg = 0; kg < 2; kg++) {
            const int kb = kg * 8;
            uint32_t af[4][4], bf[4][2];
#pragma unroll
            for (int mt = 0; mt < 4; mt++) {
                const uint32_t* ar = &As[cur][(wm + mt * 16 + g) * SSTRIDE + kb + q4];
                af[mt][0] = ar[0];
                af[mt][1] = ar[8 * SSTRIDE];
                af[mt][2] = ar[4];
                af[mt][3] = ar[8 * SSTRIDE + 4];
            }
#pragma unroll
            for (int nt = 0; nt < 4; nt++) {
                const uint32_t* br = &Bs[cur][(wn + nt * 8 + g) * SSTRIDE + kb + q4];
                bf[nt][0] = br[0];
                bf[nt][1] = br[4];
            }
#pragma unroll
            for (int mt = 0; mt < 4; mt++)
#pragma unroll
                for (int nt = 0; nt < 4; nt++)
                    mma_tf32(acc[mt][nt],
                             af[mt][0], af[mt][1], af[mt][2], af[mt][3],
                             bf[nt][0], bf[nt][1]);
        }
        if (c + 1 < nck) sstore((c + 1) & 1);
        __syncthreads();
    }

#pragma unroll
    for (int mt = 0; mt < 4; mt++) {
#pragma unroll
        for (int nt = 0; nt < 4; nt++) {
            const int col = n0 + wn + nt * 8 + 2 * q4;
            if (col >= N) continue;
            float2 bsv = make_float2(0.f, 0.f);
            if (bias) { bsv.x = bias[col]; bsv.y = bias[col + 1]; }
#pragma unroll
            for (int half = 0; half < 2; half++) {
                const int row = m0 + wm + mt * 16 + g + half * 8;
                float vx = acc[mt][nt][half * 2 + 0] + bsv.x;
                float vy = acc[mt][nt][half * 2 + 1] + bsv.y;
                if (ACT == 1) { vx = fmaxf(vx, 0.f); vy = fmaxf(vy, 0.f); }
                if (ACT == 2) { vx = tanhf(vx); vy = tanhf(vy); }
                *reinterpret_cast<float2*>(&C[(size_t)row * ldc + col]) =
                    make_float2(vx, vy);
            }
        }
    }
}

// ==================== weight prep ====================
// Build fused gate-interleaved K-major weight:
// wf[j, k] (j = unit*4 + gate) = R[k, gate*U+unit]      for k <  U
//                              = Kin[k-U, gate*U+unit]  for k >= U
__global__ void build_wf_kernel(const float* __restrict__ R,
                                const float* __restrict__ Kin,
                                const float* __restrict__ bias,
                                float* __restrict__ wf,
                                float* __restrict__ bp, int Kx)
{
    const int j = blockIdx.y;
    const int k = blockIdx.x * 256 + threadIdx.x;
    const int K = U_ + Kx;
    if (k >= K) return;
    const int oj = (j & 3) * U_ + (j >> 2);
    wf[(size_t)j * K + k] =
        (k < U_) ? R[(size_t)k * G_ + oj] : Kin[(size_t)(k - U_) * G_ + oj];
    if (k == 0) bp[j] = bias[oj];
}

__global__ void transpose_kernel(const float* __restrict__ in,
                                 float* __restrict__ out, int R, int Cc)
{
    __shared__ float t[32][33];
    const int c0 = blockIdx.x * 32, r0 = blockIdx.y * 32;
    const int x = threadIdx.x, y = threadIdx.y;
#pragma unroll
    for (int dy = 0; dy < 32; dy += 8) {
        const int r = r0 + y + dy, c = c0 + x;
        t[y + dy][x] = (r < R && c < Cc) ? in[(size_t)r * Cc + c] : 0.f;
    }
    __syncthreads();
#pragma unroll
    for (int dy = 0; dy < 32; dy += 8) {
        const int r = c0 + y + dy, c = r0 + x;
        if (r < Cc && c < R) out[(size_t)r * R + c] = t[x][y + dy];
    }
}

__global__ void zero2_kernel(float* a, float* b, int n)
{
    const int i = blockIdx.x * blockDim.x + threadIdx.x;
    if (i < n) { a[i] = 0.f; b[i] = 0.f; }
}

// ==================== host orchestration ====================
static inline dim3 ggrid(int M, int N)
{
    return dim3((N + 127) / 128, M / 128);
}

extern "C" void kernel_launch(void* const* d_in, const int* in_sizes, int n_in,
                              void* d_out, int out_size)
{
    const float* x    = (const float*)d_in[0];
    const float* m    = (const float*)d_in[1];
    const float* encK = (const float*)d_in[2];
    const float* encR = (const float*)d_in[3];
    const float* encB = (const float*)d_in[4];
    const float* decK = (const float*)d_in[5];
    const float* decR = (const float*)d_in[6];
    const float* decB = (const float*)d_in[7];
    const float* Wmap = (const float*)d_in[8];
    const float* bmap = (const float*)d_in[9];
    const float* W1   = (const float*)d_in[10];
    const float* b1   = (const float*)d_in[11];
    const float* W2   = (const float*)d_in[12];
    const float* b2   = (const float*)d_in[13];
    const float* Wo   = (const float*)d_in[14];
    const float* bo   = (const float*)d_in[15];
    float* out = (float*)d_out;

    float *h0, *h1, *c, *dec, *t1, *t2, *wT, *wfe, *wfd, *bpe, *bpd;
    cudaGetSymbolAddress((void**)&h0,  g_h0);
    cudaGetSymbolAddress((void**)&h1,  g_h1);
    cudaGetSymbolAddress((void**)&c,   g_c);
    cudaGetSymbolAddress((void**)&dec, g_dec);
    cudaGetSymbolAddress((void**)&t1,  g_b1);
    cudaGetSymbolAddress((void**)&t2,  g_b2);
    cudaGetSymbolAddress((void**)&wT,  g_wT);
    cudaGetSymbolAddress((void**)&wfe, g_wfe);
    cudaGetSymbolAddress((void**)&wfd, g_wfd);
    cudaGetSymbolAddress((void**)&bpe, g_bpe);
    cudaGetSymbolAddress((void**)&bpd, g_bpd);

    // fused recurrent weights (gate-interleaved, K-major)
    build_wf_kernel<<<dim3((KE_ + 255) / 256, G_), 256>>>(encR, encK, encB,
                                                          wfe, bpe, EIN);
    build_wf_kernel<<<dim3((KD_ + 255) / 256, G_), 256>>>(decR, decK, decB,
                                                          wfd, bpd, DIN);
    // head weights to K-major [N,K]
    dim3 tb(32, 8);
    transpose_kernel<<<dim3((H1_+31)/32, (T_*U_+31)/32), tb>>>(Wmap, wT+WT_MAP, T_*U_, H1_);
    transpose_kernel<<<dim3((H1_+31)/32, (H1_+31)/32), tb>>>(W1, wT+WT_W1, H1_, H1_);
    transpose_kernel<<<dim3((H1_+31)/32, (H1_+31)/32), tb>>>(W2, wT+WT_W2, H1_, H1_);
    transpose_kernel<<<dim3((OUT_+31)/32, (H1_+31)/32), tb>>>(Wo, wT+WT_WO, H1_, OUT_);

    {
        const int n = B_ * U_;
        zero2_kernel<<<(n + 255) / 256, 256>>>(h0, c, n);
    }

    const dim3 grS = ggrid(B_, G_);   // (12, 256)
    float* hc = h0;
    float* hn = h1;

    // encoder
    for (int t = 0; t < T_; t++) {
        lstm_step<0><<<grS, 256>>>(hc, x + (size_t)t * EIN, T_ * EIN, EIN,
                                   wfe, bpe, hn, c, nullptr, 0);
        float* tmp = hc; hc = hn; hn = tmp;
    }
    // decoder
    for (int t = 0; t < T_; t++) {
        lstm_step<1><<<grS, 256>>>(hc, m + (size_t)t * DIN, T_ * DIN, DIN,
                                   wfd, bpd, hn, c, dec, t * U_);
        float* tmp = hc; hc = hn; hn = tmp;
    }

    // dense head
    tf32_gemm<1><<<ggrid(B_, H1_), 256>>>(dec, T_ * U_, wT + WT_MAP, T_ * U_,
                                          t1, H1_, bmap, B_, H1_, T_ * U_);
    tf32_gemm<2><<<ggrid(B_, H1_), 256>>>(t1, H1_, wT + WT_W1, H1_,
                                          t2, H1_, b1, B_, H1_, H1_);
    tf32_gemm<2><<<ggrid(B_, H1_), 256>>>(t2, H1_, wT + WT_W2, H1_,
                                          t1, H1_, b2, B_, H1_, H1_);
    tf32_gemm<0><<<ggrid(B_, OUT_), 256>>>(t1, H1_, wT + WT_WO, H1_,
                                           out, OUT_, bo, B_, OUT_, H1_);
}

// round 6
// speedup vs baseline: 1.0989x; 1.0989x over previous
#include <cuda_runtime.h>
#include <math.h>
#include <stdint.h>

// ---------------- problem constants ----------------
#define B_   32768
#define T_   7
#define EIN  60
#define DIN  36
#define U_   356
#define G_   1424          // 4*U
#define H1_  768
#define OUT_ 168
#define KE_  (U_ + EIN)    // 416 fused K (encoder)
#define KD_  (U_ + DIN)    // 392 fused K (decoder)

// ---------------- scratch (device globals; total < 2 GB) -------------------
__device__ __align__(16) float g_h0  [(size_t)B_ * U_];
__device__ __align__(16) float g_h1  [(size_t)B_ * U_];
__device__ __align__(16) float g_c   [(size_t)B_ * U_];
__device__ __align__(16) float g_dec [(size_t)B_ * T_ * U_]; // 327 MB
__device__ __align__(16) float g_b1  [(size_t)B_ * H1_];
__device__ __align__(16) float g_b2  [(size_t)B_ * H1_];
// fused gate-interleaved recurrent weights, K-major [1424, K]
__device__ __align__(16) float g_wfe [G_ * KE_];
__device__ __align__(16) float g_wfd [G_ * KD_];
__device__ __align__(16) float g_bpe [G_];
__device__ __align__(16) float g_bpd [G_];
// transposed head weights (K-major [N,K])
#define WT_MAP  0                         // [768,2492]
#define WT_W1   (WT_MAP + 768*2492)       // [768,768]
#define WT_W2   (WT_W1  + 768*768)        // [768,768]
#define WT_WO   (WT_W2  + 768*768)        // [168,768]
#define WT_TOTAL (WT_WO + 168*768)
__device__ __align__(16) float g_wT[WT_TOTAL];

// ==================== tf32 helpers ====================
__device__ __forceinline__ uint32_t f2tf32(float f) {
    uint32_t u;
    asm("cvt.rna.tf32.f32 %0, %1;" : "=r"(u) : "f"(f));
    return u;
}

__device__ __forceinline__ void mma_tf32(float c[4],
                                         uint32_t a0, uint32_t a1,
                                         uint32_t a2, uint32_t a3,
                                         uint32_t b0, uint32_t b1)
{
    asm volatile(
        "mma.sync.aligned.m16n8k8.row.col.f32.tf32.tf32.f32 "
        "{%0,%1,%2,%3}, {%4,%5,%6,%7}, {%8,%9}, {%0,%1,%2,%3};"
        : "+f"(c[0]), "+f"(c[1]), "+f"(c[2]), "+f"(c[3])
        : "r"(a0), "r"(a1), "r"(a2), "r"(a3), "r"(b0), "r"(b1));
}

__device__ __forceinline__ float sigmoidf_(float v) {
    return 1.f / (1.f + expf(-v));
}

#define SSTRIDE 20   // smem row stride in words (conflict-free quad pattern)

// ==================== fused LSTM step ====================
// One tf32 GEMM over concatenated K = [h | x_t] @ Wf (gate-interleaved,
// K-major [1424, K]) with the LSTM cell in the epilogue.
// 128x128 tile, BK=16, 256 threads (8 warps 2x4, each 64x32).
// hin/hout ping-pong; c in place (block-exclusive elements); dec optional.
template<int WRITE_DEC>
__global__ void __launch_bounds__(256)
lstm_step(const float* __restrict__ hin,
          const float* __restrict__ xin, int ldx, int Kx,
          const float* __restrict__ Wf,
          const float* __restrict__ bperm,
          float* __restrict__ hout, float* __restrict__ cst,
          float* __restrict__ dec, int dec_off)
{
    __shared__ __align__(16) char sraw[40960];
    uint32_t* Ab = (uint32_t*)sraw;             // [2][128*SSTRIDE]
    uint32_t* Bb = (uint32_t*)(sraw + 20480);   // [2][128*SSTRIDE]
    float*    zs = (float*)sraw;                // epilogue overlay: 64*132 fl

    const int K  = U_ + Kx;
    const int tid  = threadIdx.x;
    const int lane = tid & 31;
    const int w    = tid >> 5;
    const int m0   = blockIdx.y * 128;
    const int n0   = blockIdx.x * 128;

    const int wm = (w >> 2) * 64;
    const int wn = (w & 3) * 32;
    const int g  = lane >> 2;
    const int q4 = lane & 3;

    const int r0s = tid >> 2;
    const int k0s = (tid & 3) * 4;
    const int r1s = r0s + 64;

    float acc[4][4][4];
#pragma unroll
    for (int i = 0; i < 4; i++)
#pragma unroll
        for (int j = 0; j < 4; j++)
#pragma unroll
            for (int q = 0; q < 4; q++) acc[i][j][q] = 0.f;

    const int nck = (K + 15) >> 4;

    float4 pa0, pa1, pb0, pb1;
    auto loadA4 = [&](int r, int k) -> float4 {
        if (k < U_)
            return *reinterpret_cast<const float4*>(
                       &hin[(size_t)(m0 + r) * U_ + k]);
        if (k < K)
            return *reinterpret_cast<const float4*>(
                       &xin[(size_t)(m0 + r) * ldx + (k - U_)]);
        return make_float4(0.f, 0.f, 0.f, 0.f);
    };
    auto gload = [&](int c) {
        const int k = c * 16 + k0s;
        pa0 = loadA4(r0s, k);
        pa1 = loadA4(r1s, k);
        const int n_0 = n0 + r0s, n_1 = n0 + r1s;
        pb0 = (k < K && n_0 < G_) ? *reinterpret_cast<const float4*>(
                                        &Wf[(size_t)n_0 * K + k])
                                  : make_float4(0.f, 0.f, 0.f, 0.f);
        pb1 = (k < K && n_1 < G_) ? *reinterpret_cast<const float4*>(
                                        &Wf[(size_t)n_1 * K + k])
                                  : make_float4(0.f, 0.f, 0.f, 0.f);
    };
    auto sstore = [&](int s) {
        uint32_t* a = &Ab[s * 128 * SSTRIDE + r0s * SSTRIDE + k0s];
        a[0] = f2tf32(pa0.x); a[1] = f2tf32(pa0.y);
        a[2] = f2tf32(pa0.z); a[3] = f2tf32(pa0.w);
        a = &Ab[s * 128 * SSTRIDE + r1s * SSTRIDE + k0s];
        a[0] = f2tf32(pa1.x); a[1] = f2tf32(pa1.y);
        a[2] = f2tf32(pa1.z); a[3] = f2tf32(pa1.w);
        uint32_t* b = &Bb[s * 128 * SSTRIDE + r0s * SSTRIDE + k0s];
        b[0] = f2tf32(pb0.x); b[1] = f2tf32(pb0.y);
        b[2] = f2tf32(pb0.z); b[3] = f2tf32(pb0.w);
        b = &Bb[s * 128 * SSTRIDE + r1s * SSTRIDE + k0s];
        b[0] = f2tf32(pb1.x); b[1] = f2tf32(pb1.y);
        b[2] = f2tf32(pb1.z); b[3] = f2tf32(pb1.w);
    };

    gload(0);
    sstore(0);
    __syncthreads();

    for (int c = 0; c < nck; c++) {
        const int cur = c & 1;
        if (c + 1 < nck) gload(c + 1);
#pragma unroll
        for (int kg = 0; kg < 2; kg++) {
            const int kb = kg * 8;
            uint32_t af[4][4], bf[4][2];
#pragma unroll
            for (int mt = 0; mt < 4; mt++) {
                const uint32_t* ar =
                    &Ab[cur * 128 * SSTRIDE + (wm + mt * 16 + g) * SSTRIDE + kb + q4];
                af[mt][0] = ar[0];
                af[mt][1] = ar[8 * SSTRIDE];
                af[mt][2] = ar[4];
                af[mt][3] = ar[8 * SSTRIDE + 4];
            }
#pragma unroll
            for (int nt = 0; nt < 4; nt++) {
                const uint32_t* br =
                    &Bb[cur * 128 * SSTRIDE + (wn + nt * 8 + g) * SSTRIDE + kb + q4];
                bf[nt][0] = br[0];
                bf[nt][1] = br[4];
            }
#pragma unroll
            for (int mt = 0; mt < 4; mt++)
#pragma unroll
                for (int nt = 0; nt < 4; nt++)
                    mma_tf32(acc[mt][nt],
                             af[mt][0], af[mt][1], af[mt][2], af[mt][3],
                             bf[nt][0], bf[nt][1]);
        }
        if (c + 1 < nck) sstore((c + 1) & 1);
        __syncthreads();
    }

    // ---- epilogue: z -> smem (64-row halves) -> LSTM cell ----
    // COALESCED mapping: unit is the fast lane index (32 consecutive units
    // per warp -> one 128B line in c/h/dec).
    const int ubase = n0 >> 2;      // first unit of this tile
    const int ul = tid & 31;        // unit-in-tile (lane-fast)
    const int rb = tid >> 5;        // row group 0..7
    const int unit = ubase + ul;
#pragma unroll
    for (int half = 0; half < 2; half++) {
        if ((w >> 2) == half) {
#pragma unroll
            for (int mt = 0; mt < 4; mt++) {
#pragma unroll
                for (int nt = 0; nt < 4; nt++) {
                    const int col = n0 + wn + nt * 8 + 2 * q4;
                    if (col >= G_) continue;
                    const float bx = bperm[col], by = bperm[col + 1];
                    const int cr = wn + nt * 8 + 2 * q4;
                    const int rl = mt * 16 + g;
                    zs[rl * 132 + cr]           = acc[mt][nt][0] + bx;
                    zs[rl * 132 + cr + 1]       = acc[mt][nt][1] + by;
                    zs[(rl + 8) * 132 + cr]     = acc[mt][nt][2] + bx;
                    zs[(rl + 8) * 132 + cr + 1] = acc[mt][nt][3] + by;
                }
            }
        }
        __syncthreads();
        if (unit < U_) {
#pragma unroll
            for (int rr = 0; rr < 8; rr++) {
                const int rl = rr * 8 + rb;
                const int b = m0 + half * 64 + rl;
                const float4 zv =
                    *reinterpret_cast<const float4*>(&zs[rl * 132 + ul * 4]);
                const float iv = sigmoidf_(zv.x);
                const float fv = sigmoidf_(zv.y);
                const float gv = tanhf(zv.z);
                const float ov = sigmoidf_(zv.w);
                const size_t ci = (size_t)b * U_ + unit;
                const float cn = fv * cst[ci] + iv * gv;
                const float hn = ov * tanhf(cn);
                cst[ci] = cn;
                hout[ci] = hn;
                if (WRITE_DEC)
                    dec[(size_t)b * (T_ * U_) + dec_off + unit] = hn;
            }
        }
        __syncthreads();
    }
}

// ==================== tf32 mma.sync GEMM (head) ====================
template<int ACT> // 0 none, 1 relu, 2 tanh
__global__ void __launch_bounds__(256)
tf32_gemm(const float* __restrict__ A, int lda,
          const float* __restrict__ Bt, int ldb,
          float* __restrict__ C, int ldc,
          const float* __restrict__ bias,
          int M, int N, int K)
{
    __shared__ uint32_t As[2][128 * SSTRIDE];
    __shared__ uint32_t Bs[2][128 * SSTRIDE];

    const int tid  = threadIdx.x;
    const int lane = tid & 31;
    const int w    = tid >> 5;
    const int m0   = blockIdx.y * 128;
    const int n0   = blockIdx.x * 128;

    const int wm = (w >> 2) * 64;
    const int wn = (w & 3) * 32;
    const int g  = lane >> 2;
    const int q4 = lane & 3;

    const int r0s = tid >> 2;
    const int k0s = (tid & 3) * 4;
    const int r1s = r0s + 64;

    float acc[4][4][4];
#pragma unroll
    for (int i = 0; i < 4; i++)
#pragma unroll
        for (int j = 0; j < 4; j++)
#pragma unroll
            for (int q = 0; q < 4; q++) acc[i][j][q] = 0.f;

    const int nck = (K + 15) >> 4;

    float4 pa0, pa1, pb0, pb1;
    auto gload = [&](int c) {
        const int k = c * 16 + k0s;
        pa0 = (k < K) ? *reinterpret_cast<const float4*>(
                            &A[(size_t)(m0 + r0s) * lda + k])
                      : make_float4(0.f, 0.f, 0.f, 0.f);
        pa1 = (k < K) ? *reinterpret_cast<const float4*>(
                            &A[(size_t)(m0 + r1s) * lda + k])
                      : make_float4(0.f, 0.f, 0.f, 0.f);
        const int n_0 = n0 + r0s, n_1 = n0 + r1s;
        pb0 = (k < K && n_0 < N) ? *reinterpret_cast<const float4*>(
                                       &Bt[(size_t)n_0 * ldb + k])
                                 : make_float4(0.f, 0.f, 0.f, 0.f);
        pb1 = (k < K && n_1 < N) ? *reinterpret_cast<const float4*>(
                                       &Bt[(size_t)n_1 * ldb + k])
                                 : make_float4(0.f, 0.f, 0.f, 0.f);
    };
    auto sstore = [&](int s) {
        uint32_t* a = &As[s][r0s * SSTRIDE + k0s];
        a[0] = f2tf32(pa0.x); a[1] = f2tf32(pa0.y);
        a[2] = f2tf32(pa0.z); a[3] = f2tf32(pa0.w);
        a = &As[s][r1s * SSTRIDE + k0s];
        a[0] = f2tf32(pa1.x); a[1] = f2tf32(pa1.y);
        a[2] = f2tf32(pa1.z); a[3] = f2tf32(pa1.w);
        uint32_t* b = &Bs[s][r0s * SSTRIDE + k0s];
        b[0] = f2tf32(pb0.x); b[1] = f2tf32(pb0.y);
        b[2] = f2tf32(pb0.z); b[3] = f2tf32(pb0.w);
        b = &Bs[s][r1s * SSTRIDE + k0s];
        b[0] = f2tf32(pb1.x); b[1] = f2tf32(pb1.y);
        b[2] = f2tf32(pb1.z); b[3] = f2tf32(pb1.w);
    };

    gload(0);
    sstore(0);
    __syncthreads();

    for (int c = 0; c < nck; c++) {
        const int cur = c & 1;
        if (c + 1 < nck) gload(c + 1);
#pragma unroll
        for (int kg = 0; kg < 2; kg++) {
            const int kb = kg * 8;
            uint32_t af[4][4], bf[4][2];
#pragma unroll
            for (int mt = 0; mt < 4; mt++) {
                const uint32_t* ar = &As[cur][(wm + mt * 16 + g) * SSTRIDE + kb + q4];
                af[mt][0] = ar[0];
                af[mt][1] = ar[8 * SSTRIDE];
                af[mt][2] = ar[4];
                af[mt][3] = ar[8 * SSTRIDE + 4];
            }
#pragma unroll
            for (int nt = 0; nt < 4; nt++) {
                const uint32_t* br = &Bs[cur][(wn + nt * 8 + g) * SSTRIDE + kb + q4];
                bf[nt][0] = br[0];
                bf[nt][1] = br[4];
            }
#pragma unroll
            for (int mt = 0; mt < 4; mt++)
#pragma unroll
                for (int nt = 0; nt < 4; nt++)
                    mma_tf32(acc[mt][nt],
                             af[mt][0], af[mt][1], af[mt][2], af[mt][3],
                             bf[nt][0], bf[nt][1]);
        }
        if (c + 1 < nck) sstore((c + 1) & 1);
        __syncthreads();
    }

#pragma unroll
    for (int mt = 0; mt < 4; mt++) {
#pragma unroll
        for (int nt = 0; nt < 4; nt++) {
            const int col = n0 + wn + nt * 8 + 2 * q4;
            if (col >= N) continue;
            float2 bsv = make_float2(0.f, 0.f);
            if (bias) { bsv.x = bias[col]; bsv.y = bias[col + 1]; }
#pragma unroll
            for (int half = 0; half < 2; half++) {
                const int row = m0 + wm + mt * 16 + g + half * 8;
                float vx = acc[mt][nt][half * 2 + 0] + bsv.x;
                float vy = acc[mt][nt][half * 2 + 1] + bsv.y;
                if (ACT == 1) { vx = fmaxf(vx, 0.f); vy = fmaxf(vy, 0.f); }
                if (ACT == 2) { vx = tanhf(vx); vy = tanhf(vy); }
                *reinterpret_cast<float2*>(&C[(size_t)row * ldc + col]) =
                    make_float2(vx, vy);
            }
        }
    }
}

// ==================== weight prep ====================
// Build fused gate-interleaved K-major weight:
// wf[j, k] (j = unit*4 + gate) = R[k, gate*U+unit]      for k <  U
//                              = Kin[k-U, gate*U+unit]  for k >= U
__global__ void build_wf_kernel(const float* __restrict__ R,
                                const float* __restrict__ Kin,
                                const float* __restrict__ bias,
                                float* __restrict__ wf,
                                float* __restrict__ bp, int Kx)
{
    const int j = blockIdx.y;
    const int k = blockIdx.x * 256 + threadIdx.x;
    const int K = U_ + Kx;
    if (k >= K) return;
    const int oj = (j & 3) * U_ + (j >> 2);
    wf[(size_t)j * K + k] =
        (k < U_) ? R[(size_t)k * G_ + oj] : Kin[(size_t)(k - U_) * G_ + oj];
    if (k == 0) bp[j] = bias[oj];
}

__global__ void transpose_kernel(const float* __restrict__ in,
                                 float* __restrict__ out, int R, int Cc)
{
    __shared__ float t[32][33];
    const int c0 = blockIdx.x * 32, r0 = blockIdx.y * 32;
    const int x = threadIdx.x, y = threadIdx.y;
#pragma unroll
    for (int dy = 0; dy < 32; dy += 8) {
        const int r = r0 + y + dy, c = c0 + x;
        t[y + dy][x] = (r < R && c < Cc) ? in[(size_t)r * Cc + c] : 0.f;
    }
    __syncthreads();
#pragma unroll
    for (int dy = 0; dy < 32; dy += 8) {
        const int r = c0 + y + dy, c = r0 + x;
        if (r < Cc && c < R) out[(size_t)r * R + c] = t[x][y + dy];
    }
}

__global__ void zero2_kernel(float* a, float* b, int n)
{
    const int i = blockIdx.x * blockDim.x + threadIdx.x;
    if (i < n) { a[i] = 0.f; b[i] = 0.f; }
}

// ==================== host orchestration ====================
static inline dim3 ggrid(int M, int N)
{
    return dim3((N + 127) / 128, M / 128);
}

extern "C" void kernel_launch(void* const* d_in, const int* in_sizes, int n_in,
                              void* d_out, int out_size)
{
    const float* x    = (const float*)d_in[0];
    const float* m    = (const float*)d_in[1];
    const float* encK = (const float*)d_in[2];
    const float* encR = (const float*)d_in[3];
    const float* encB = (const float*)d_in[4];
    const float* decK = (const float*)d_in[5];
    const float* decR = (const float*)d_in[6];
    const float* decB = (const float*)d_in[7];
    const float* Wmap = (const float*)d_in[8];
    const float* bmap = (const float*)d_in[9];
    const float* W1   = (const float*)d_in[10];
    const float* b1   = (const float*)d_in[11];
    const float* W2   = (const float*)d_in[12];
    const float* b2   = (const float*)d_in[13];
    const float* Wo   = (const float*)d_in[14];
    const float* bo   = (const float*)d_in[15];
    float* out = (float*)d_out;

    float *h0, *h1, *c, *dec, *t1, *t2, *wT, *wfe, *wfd, *bpe, *bpd;
    cudaGetSymbolAddress((void**)&h0,  g_h0);
    cudaGetSymbolAddress((void**)&h1,  g_h1);
    cudaGetSymbolAddress((void**)&c,   g_c);
    cudaGetSymbolAddress((void**)&dec, g_dec);
    cudaGetSymbolAddress((void**)&t1,  g_b1);
    cudaGetSymbolAddress((void**)&t2,  g_b2);
    cudaGetSymbolAddress((void**)&wT,  g_wT);
    cudaGetSymbolAddress((void**)&wfe, g_wfe);
    cudaGetSymbolAddress((void**)&wfd, g_wfd);
    cudaGetSymbolAddress((void**)&bpe, g_bpe);
    cudaGetSymbolAddress((void**)&bpd, g_bpd);

    // fused recurrent weights (gate-interleaved, K-major)
    build_wf_kernel<<<dim3((KE_ + 255) / 256, G_), 256>>>(encR, encK, encB,
                                                          wfe, bpe, EIN);
    build_wf_kernel<<<dim3((KD_ + 255) / 256, G_), 256>>>(decR, decK, decB,
                                                          wfd, bpd, DIN);
    // head weights to K-major [N,K]
    dim3 tb(32, 8);
    transpose_kernel<<<dim3((H1_+31)/32, (T_*U_+31)/32), tb>>>(Wmap, wT+WT_MAP, T_*U_, H1_);
    transpose_kernel<<<dim3((H1_+31)/32, (H1_+31)/32), tb>>>(W1, wT+WT_W1, H1_, H1_);
    transpose_kernel<<<dim3((H1_+31)/32, (H1_+31)/32), tb>>>(W2, wT+WT_W2, H1_, H1_);
    transpose_kernel<<<dim3((OUT_+31)/32, (H1_+31)/32), tb>>>(Wo, wT+WT_WO, H1_, OUT_);

    {
        const int n = B_ * U_;
        zero2_kernel<<<(n + 255) / 256, 256>>>(h0, c, n);
    }

    const dim3 grS = ggrid(B_, G_);   // (12, 256)
    float* hc = h0;
    float* hn = h1;

    // encoder
    for (int t = 0; t < T_; t++) {
        lstm_step<0><<<grS, 256>>>(hc, x + (size_t)t * EIN, T_ * EIN, EIN,
                                   wfe, bpe, hn, c, nullptr, 0);
        float* tmp = hc; hc = hn; hn = tmp;
    }
    // decoder
    for (int t = 0; t < T_; t++) {
        lstm_step<1><<<grS, 256>>>(hc, m + (size_t)t * DIN, T_ * DIN, DIN,
                                   wfd, bpd, hn, c, dec, t * U_);
        float* tmp = hc; hc = hn; hn = tmp;
    }

    // dense head
    tf32_gemm<1><<<ggrid(B_, H1_), 256>>>(dec, T_ * U_, wT + WT_MAP, T_ * U_,
                                          t1, H1_, bmap, B_, H1_, T_ * U_);
    tf32_gemm<2><<<ggrid(B_, H1_), 256>>>(t1, H1_, wT + WT_W1, H1_,
                                          t2, H1_, b1, B_, H1_, H1_);
    tf32_gemm<2><<<ggrid(B_, H1_), 256>>>(t2, H1_, wT + WT_W2, H1_,
                                          t1, H1_, b2, B_, H1_, H1_);
    tf32_gemm<0><<<ggrid(B_, OUT_), 256>>>(t1, H1_, wT + WT_WO, H1_,
                                           out, OUT_, bo, B_, OUT_, H1_);
}

// round 7
// speedup vs baseline: 1.9489x; 1.7735x over previous
#include <cuda_runtime.h>
#include <cuda_fp16.h>
#include <math.h>
#include <stdint.h>

// ---------------- problem constants ----------------
#define B_   32768
#define T_   7
#define EIN  60
#define DIN  36
#define U_   356
#define G_   1424          // 4*U
#define H1_  768
#define OUT_ 168
#define HS   360           // padded h width (halves, mult of 8)
#define XS   64            // padded x width
#define KAP  448           // fused K padded (mult of 32)
#define DECS 2496          // padded dec row (7*356=2492 -> 2496)
#define NCKS (KAP / 32)    // 14 chunks per LSTM step

// ---------------- scratch (device globals) ----------------------------
__device__ __align__(16) __half g_h0 [(size_t)B_ * HS];
__device__ __align__(16) __half g_h1 [(size_t)B_ * HS];
__device__ __align__(16) float  g_c  [(size_t)B_ * U_];
__device__ __align__(16) __half g_dec[(size_t)B_ * DECS];    // 163 MB
__device__ __align__(16) __half g_t1 [(size_t)B_ * H1_];
__device__ __align__(16) __half g_t2 [(size_t)B_ * H1_];
__device__ __align__(16) __half g_xe [(size_t)B_ * T_ * XS]; // enc x, padded
__device__ __align__(16) __half g_xd [(size_t)B_ * T_ * XS]; // dec m, padded
// gate-interleaved fused recurrent weights [1424][KAP] (half)
__device__ __align__(16) __half g_wfe[(size_t)G_ * KAP];
__device__ __align__(16) __half g_wfd[(size_t)G_ * KAP];
__device__ __align__(16) float  g_bpe[G_];
__device__ __align__(16) float  g_bpd[G_];
// transposed head weights (K-major, padded lda)
#define WT_MAP  0                             // [768][2496]
#define WT_W1   (WT_MAP + 768*DECS)           // [768][768]
#define WT_W2   (WT_W1  + 768*768)
#define WT_WO   (WT_W2  + 768*768)            // [168][768]
#define WT_TOTAL (WT_WO + 168*768)
__device__ __align__(16) __half g_wT[WT_TOTAL];

// ==================== helpers ====================
__device__ __forceinline__ uint32_t smem_u32(const void* p) {
    uint32_t a;
    asm("{ .reg .u64 t; cvta.to.shared.u64 t, %1; cvt.u32.u64 %0, t; }"
        : "=r"(a) : "l"(p));
    return a;
}
__device__ __forceinline__ void cpa16(uint32_t dst, const void* src, uint32_t sz) {
    asm volatile("cp.async.cg.shared.global [%0], [%1], 16, %2;"
                 :: "r"(dst), "l"(src), "r"(sz));
}
__device__ __forceinline__ void cpa_commit() {
    asm volatile("cp.async.commit_group;" ::: "memory");
}
__device__ __forceinline__ void cpa_wait(int ahead) {
    if (ahead >= 2)      asm volatile("cp.async.wait_group 2;" ::: "memory");
    else if (ahead == 1) asm volatile("cp.async.wait_group 1;" ::: "memory");
    else                 asm volatile("cp.async.wait_group 0;" ::: "memory");
}
__device__ __forceinline__ void mma_f16(float c[4],
                                        uint32_t a0, uint32_t a1,
                                        uint32_t a2, uint32_t a3,
                                        uint32_t b0, uint32_t b1)
{
    asm volatile(
        "mma.sync.aligned.m16n8k16.row.col.f32.f16.f16.f32 "
        "{%0,%1,%2,%3}, {%4,%5,%6,%7}, {%8,%9}, {%0,%1,%2,%3};"
        : "+f"(c[0]), "+f"(c[1]), "+f"(c[2]), "+f"(c[3])
        : "r"(a0), "r"(a1), "r"(a2), "r"(a3), "r"(b0), "r"(b1));
}
__device__ __forceinline__ float sigmoidf_(float v) {
    return 1.f / (1.f + expf(-v));
}
__device__ __forceinline__ void store2(__half* p, float x, float y) {
    *reinterpret_cast<__half2*>(p) = __floats2half2_rn(x, y);
}
__device__ __forceinline__ void store2(float* p, float x, float y) {
    *reinterpret_cast<float2*>(p) = make_float2(x, y);
}

// smem tile: 128 rows x 20 words (32 halves used + 8 pad), per operand
#define ROWW   20                    // words per row
#define TILE_W (128 * ROWW)          // 2560 words = 10240 B
#define STG_W  (2 * TILE_W)          // A+B per stage, words
#define DSMEM  (3 * STG_W * 4)       // 61440 B

// ==================== fused LSTM step (fp16, cp.async) ====================
// K layout: [0,360) h (padded), [360,424) x (padded), [424,448) zero.
template<int WRITE_DEC>
__global__ void __launch_bounds__(256)
lstm_step(const __half* __restrict__ hin,
          const __half* __restrict__ xin,       // + t*XS, stride T_*XS
          const __half* __restrict__ Wf,
          const float* __restrict__ bperm,
          __half* __restrict__ hout, float* __restrict__ cst,
          __half* __restrict__ dec, int dec_off)
{
    extern __shared__ __align__(16) char dynsmem[];
    uint32_t* smw = (uint32_t*)dynsmem;
    const uint32_t sb = smem_u32(dynsmem);

    const int tid  = threadIdx.x;
    const int lane = tid & 31;
    const int w    = tid >> 5;
    const int m0   = blockIdx.y * 128;
    const int n0   = blockIdx.x * 128;

    const int wm = (w >> 2) * 64;
    const int wn = (w & 3) * 32;
    const int g  = lane >> 2;
    const int q4 = lane & 3;

    const int rs = tid >> 2;         // 0..63
    const int kq = tid & 3;

    float acc[4][4][4];
#pragma unroll
    for (int i = 0; i < 4; i++)
#pragma unroll
        for (int j = 0; j < 4; j++)
#pragma unroll
            for (int q = 0; q < 4; q++) acc[i][j][q] = 0.f;

    auto issue = [&](int c) {
        const int s  = c % 3;
        const int kh = c * 32 + kq * 8;
        const uint32_t base = sb + (uint32_t)(s * STG_W * 4);
#pragma unroll
        for (int rr = 0; rr < 2; rr++) {
            const int r = rs + rr * 64;
            const uint32_t da = base + (uint32_t)(r * ROWW * 4 + kq * 16);
            const void* asrc;
            uint32_t asz = 16;
            if (kh < HS)            asrc = hin + (size_t)(m0 + r) * HS + kh;
            else if (kh < HS + XS)  asrc = xin + (size_t)(m0 + r) * (T_ * XS) + (kh - HS);
            else { asrc = hin; asz = 0; }
            cpa16(da, asrc, asz);
            const int n = n0 + r;
            const void* bsrc = (n < G_) ? (const void*)(Wf + (size_t)n * KAP + kh)
                                        : (const void*)Wf;
            cpa16(da + TILE_W * 4, bsrc, (n < G_) ? 16u : 0u);
        }
        cpa_commit();
    };

    issue(0);
    issue(1);

    for (int c = 0; c < NCKS; c++) {
        if (c + 2 < NCKS) issue(c + 2);
        const int last = (NCKS - 1 < c + 2) ? NCKS - 1 : c + 2;
        cpa_wait(last - c);
        __syncthreads();

        const int st  = (c % 3) * STG_W;
        const int stB = st + TILE_W;
#pragma unroll
        for (int kg = 0; kg < 2; kg++) {
            const int kb = kg * 8;
            uint32_t af[4][4], bf[4][2];
#pragma unroll
            for (int mt = 0; mt < 4; mt++) {
                const uint32_t* ar = smw + st + (wm + mt * 16 + g) * ROWW + kb + q4;
                af[mt][0] = ar[0];
                af[mt][1] = ar[8 * ROWW];
                af[mt][2] = ar[4];
                af[mt][3] = ar[8 * ROWW + 4];
            }
#pragma unroll
            for (int nt = 0; nt < 4; nt++) {
                const uint32_t* br = smw + stB + (wn + nt * 8 + g) * ROWW + kb + q4;
                bf[nt][0] = br[0];
                bf[nt][1] = br[4];
            }
#pragma unroll
            for (int mt = 0; mt < 4; mt++)
#pragma unroll
                for (int nt = 0; nt < 4; nt++)
                    mma_f16(acc[mt][nt],
                            af[mt][0], af[mt][1], af[mt][2], af[mt][3],
                            bf[nt][0], bf[nt][1]);
        }
        __syncthreads();
    }

    // ---- epilogue: z -> smem halves -> LSTM cell (unit lane-fast) ----
    float* zs = (float*)dynsmem;     // 64*132 floats
    const int ubase = n0 >> 2;
    const int ul = tid & 31;
    const int rb = tid >> 5;
    const int unit = ubase + ul;
#pragma unroll
    for (int half = 0; half < 2; half++) {
        if ((w >> 2) == half) {
#pragma unroll
            for (int mt = 0; mt < 4; mt++) {
#pragma unroll
                for (int nt = 0; nt < 4; nt++) {
                    const int col = n0 + wn + nt * 8 + 2 * q4;
                    if (col >= G_) continue;
                    const float bx = bperm[col], by = bperm[col + 1];
                    const int cr = wn + nt * 8 + 2 * q4;
                    const int rl = mt * 16 + g;
                    zs[rl * 132 + cr]           = acc[mt][nt][0] + bx;
                    zs[rl * 132 + cr + 1]       = acc[mt][nt][1] + by;
                    zs[(rl + 8) * 132 + cr]     = acc[mt][nt][2] + bx;
                    zs[(rl + 8) * 132 + cr + 1] = acc[mt][nt][3] + by;
                }
            }
        }
        __syncthreads();
        if (unit < U_) {
#pragma unroll
            for (int rr = 0; rr < 8; rr++) {
                const int rl = rr * 8 + rb;
                const int b = m0 + half * 64 + rl;
                const float4 zv =
                    *reinterpret_cast<const float4*>(&zs[rl * 132 + ul * 4]);
                const float iv = sigmoidf_(zv.x);
                const float fv = sigmoidf_(zv.y);
                const float gv = tanhf(zv.z);
                const float ov = sigmoidf_(zv.w);
                const size_t ci = (size_t)b * U_ + unit;
                const float cn = fv * cst[ci] + iv * gv;
                const float hn = ov * tanhf(cn);
                cst[ci] = cn;
                hout[(size_t)b * HS + unit] = __float2half_rn(hn);
                if (WRITE_DEC)
                    dec[(size_t)b * DECS + dec_off + unit] = __float2half_rn(hn);
            }
        }
        __syncthreads();
    }
}

// ==================== fp16 GEMM (head) ====================
// C = act(A @ Bt^T + bias). A [M][lda] half (lda padded, all loads valid),
// Bt [N][ldb] half (padded). K multiple of 32. N guarded.
template<int ACT, typename TO> // ACT: 0 none, 1 relu, 2 tanh
__global__ void __launch_bounds__(256)
hgemm(const __half* __restrict__ A, int lda,
      const __half* __restrict__ Bt, int ldb,
      TO* __restrict__ C, int ldc,
      const float* __restrict__ bias,
      int N, int K)
{
    extern __shared__ __align__(16) char dynsmem[];
    uint32_t* smw = (uint32_t*)dynsmem;
    const uint32_t sb = smem_u32(dynsmem);

    const int tid  = threadIdx.x;
    const int lane = tid & 31;
    const int w    = tid >> 5;
    const int m0   = blockIdx.y * 128;
    const int n0   = blockIdx.x * 128;

    const int wm = (w >> 2) * 64;
    const int wn = (w & 3) * 32;
    const int g  = lane >> 2;
    const int q4 = lane & 3;

    const int rs = tid >> 2;
    const int kq = tid & 3;

    float acc[4][4][4];
#pragma unroll
    for (int i = 0; i < 4; i++)
#pragma unroll
        for (int j = 0; j < 4; j++)
#pragma unroll
            for (int q = 0; q < 4; q++) acc[i][j][q] = 0.f;

    const int nck = K >> 5;

    auto issue = [&](int c) {
        const int s  = c % 3;
        const int kh = c * 32 + kq * 8;
        const uint32_t base = sb + (uint32_t)(s * STG_W * 4);
#pragma unroll
        for (int rr = 0; rr < 2; rr++) {
            const int r = rs + rr * 64;
            const uint32_t da = base + (uint32_t)(r * ROWW * 4 + kq * 16);
            cpa16(da, A + (size_t)(m0 + r) * lda + kh, 16);
            const int n = n0 + r;
            const void* bsrc = (n < N) ? (const void*)(Bt + (size_t)n * ldb + kh)
                                       : (const void*)Bt;
            cpa16(da + TILE_W * 4, bsrc, (n < N) ? 16u : 0u);
        }
        cpa_commit();
    };

    issue(0);
    issue(1);

    for (int c = 0; c < nck; c++) {
        if (c + 2 < nck) issue(c + 2);
        const int last = (nck - 1 < c + 2) ? nck - 1 : c + 2;
        cpa_wait(last - c);
        __syncthreads();

        const int st  = (c % 3) * STG_W;
        const int stB = st + TILE_W;
#pragma unroll
        for (int kg = 0; kg < 2; kg++) {
            const int kb = kg * 8;
            uint32_t af[4][4], bf[4][2];
#pragma unroll
            for (int mt = 0; mt < 4; mt++) {
                const uint32_t* ar = smw + st + (wm + mt * 16 + g) * ROWW + kb + q4;
                af[mt][0] = ar[0];
                af[mt][1] = ar[8 * ROWW];
                af[mt][2] = ar[4];
                af[mt][3] = ar[8 * ROWW + 4];
            }
#pragma unroll
            for (int nt = 0; nt < 4; nt++) {
                const uint32_t* br = smw + stB + (wn + nt * 8 + g) * ROWW + kb + q4;
                bf[nt][0] = br[0];
                bf[nt][1] = br[4];
            }
#pragma unroll
            for (int mt = 0; mt < 4; mt++)
#pragma unroll
                for (int nt = 0; nt < 4; nt++)
                    mma_f16(acc[mt][nt],
                            af[mt][0], af[mt][1], af[mt][2], af[mt][3],
                            bf[nt][0], bf[nt][1]);
        }
        __syncthreads();
    }

#pragma unroll
    for (int mt = 0; mt < 4; mt++) {
#pragma unroll
        for (int nt = 0; nt < 4; nt++) {
            const int col = n0 + wn + nt * 8 + 2 * q4;
            if (col >= N) continue;
            const float bx = bias ? bias[col] : 0.f;
            const float by = bias ? bias[col + 1] : 0.f;
#pragma unroll
            for (int half = 0; half < 2; half++) {
                const int row = m0 + wm + mt * 16 + g + half * 8;
                float vx = acc[mt][nt][half * 2 + 0] + bx;
                float vy = acc[mt][nt][half * 2 + 1] + by;
                if (ACT == 1) { vx = fmaxf(vx, 0.f); vy = fmaxf(vy, 0.f); }
                if (ACT == 2) { vx = tanhf(vx); vy = tanhf(vy); }
                store2(&C[(size_t)row * ldc + col], vx, vy);
            }
        }
    }
}

// ==================== prep kernels ====================
__global__ void cvt_x_kernel(const float* __restrict__ x,
                             __half* __restrict__ xh, int W)
{
    const int i = blockIdx.x * 256 + threadIdx.x;
    if (i >= B_ * T_ * XS) return;
    const int j = i & (XS - 1);
    const int bt = i >> 6;
    xh[i] = (j < W) ? __float2half_rn(x[(size_t)bt * W + j]) : __float2half_rn(0.f);
}

// wf[j][k]: k<356 -> R[k][oj]; 360<=k<360+Kx -> Kin[k-360][oj]; else 0
__global__ void build_wf_kernel(const float* __restrict__ R,
                                const float* __restrict__ Kin,
                                const float* __restrict__ bias,
                                __half* __restrict__ wf,
                                float* __restrict__ bp, int Kx)
{
    const int j = blockIdx.y;
    const int k = blockIdx.x * 256 + threadIdx.x;
    if (k >= KAP) return;
    const int oj = (j & 3) * U_ + (j >> 2);
    float v = 0.f;
    if (k < U_)                      v = R[(size_t)k * G_ + oj];
    else if (k >= HS && k < HS + Kx) v = Kin[(size_t)(k - HS) * G_ + oj];
    wf[(size_t)j * KAP + k] = __float2half_rn(v);
    if (k == 0) bp[j] = bias[oj];
}

// out[c][ldo] = in[r][c] (half), zero-padded for r >= R
__global__ void transpose_h_kernel(const float* __restrict__ in,
                                   __half* __restrict__ out,
                                   int R, int Cc, int ldo)
{
    __shared__ float t[32][33];
    const int c0 = blockIdx.x * 32, r0 = blockIdx.y * 32;
    const int x = threadIdx.x, y = threadIdx.y;
#pragma unroll
    for (int dy = 0; dy < 32; dy += 8) {
        const int r = r0 + y + dy, c = c0 + x;
        t[y + dy][x] = (r < R && c < Cc) ? in[(size_t)r * Cc + c] : 0.f;
    }
    __syncthreads();
#pragma unroll
    for (int dy = 0; dy < 32; dy += 8) {
        const int r = c0 + y + dy, c = r0 + x;
        if (r < Cc && c < ldo)
            out[(size_t)r * ldo + c] = __float2half_rn(c < R ? t[x][y + dy] : 0.f);
    }
}

__global__ void zero_hc_kernel(__half* h, float* c)
{
    const int i = blockIdx.x * 256 + threadIdx.x;
    if (i < B_ * HS) h[i] = __float2half_rn(0.f);
    if (i < B_ * U_) c[i] = 0.f;
}

// ==================== host orchestration ====================
extern "C" void kernel_launch(void* const* d_in, const int* in_sizes, int n_in,
                              void* d_out, int out_size)
{
    const float* x    = (const float*)d_in[0];
    const float* m    = (const float*)d_in[1];
    const float* encK = (const float*)d_in[2];
    const float* encR = (const float*)d_in[3];
    const float* encB = (const float*)d_in[4];
    const float* decK = (const float*)d_in[5];
    const float* decR = (const float*)d_in[6];
    const float* decB = (const float*)d_in[7];
    const float* Wmap = (const float*)d_in[8];
    const float* bmap = (const float*)d_in[9];
    const float* W1   = (const float*)d_in[10];
    const float* b1   = (const float*)d_in[11];
    const float* W2   = (const float*)d_in[12];
    const float* b2   = (const float*)d_in[13];
    const float* Wo   = (const float*)d_in[14];
    const float* bo   = (const float*)d_in[15];
    float* out = (float*)d_out;

    __half *h0, *h1, *dec, *t1, *t2, *xe, *xd, *wfe, *wfd, *wT;
    float *c, *bpe, *bpd;
    cudaGetSymbolAddress((void**)&h0,  g_h0);
    cudaGetSymbolAddress((void**)&h1,  g_h1);
    cudaGetSymbolAddress((void**)&c,   g_c);
    cudaGetSymbolAddress((void**)&dec, g_dec);
    cudaGetSymbolAddress((void**)&t1,  g_t1);
    cudaGetSymbolAddress((void**)&t2,  g_t2);
    cudaGetSymbolAddress((void**)&xe,  g_xe);
    cudaGetSymbolAddress((void**)&xd,  g_xd);
    cudaGetSymbolAddress((void**)&wfe, g_wfe);
    cudaGetSymbolAddress((void**)&wfd, g_wfd);
    cudaGetSymbolAddress((void**)&bpe, g_bpe);
    cudaGetSymbolAddress((void**)&bpd, g_bpd);
    cudaGetSymbolAddress((void**)&wT,  g_wT);

    cudaFuncSetAttribute(lstm_step<0>, cudaFuncAttributeMaxDynamicSharedMemorySize, DSMEM);
    cudaFuncSetAttribute(lstm_step<1>, cudaFuncAttributeMaxDynamicSharedMemorySize, DSMEM);
    cudaFuncSetAttribute(hgemm<1, __half>, cudaFuncAttributeMaxDynamicSharedMemorySize, DSMEM);
    cudaFuncSetAttribute(hgemm<2, __half>, cudaFuncAttributeMaxDynamicSharedMemorySize, DSMEM);
    cudaFuncSetAttribute(hgemm<0, float>,  cudaFuncAttributeMaxDynamicSharedMemorySize, DSMEM);

    // ---- prep ----
    {
        const int nx = B_ * T_ * XS;
        cvt_x_kernel<<<(nx + 255) / 256, 256>>>(x, xe, EIN);
        cvt_x_kernel<<<(nx + 255) / 256, 256>>>(m, xd, DIN);
    }
    build_wf_kernel<<<dim3((KAP + 255) / 256, G_), 256>>>(encR, encK, encB, wfe, bpe, EIN);
    build_wf_kernel<<<dim3((KAP + 255) / 256, G_), 256>>>(decR, decK, decB, wfd, bpd, DIN);
    {
        dim3 tb(32, 8);
        transpose_h_kernel<<<dim3((H1_+31)/32, (DECS+31)/32), tb>>>(Wmap, wT+WT_MAP, T_*U_, H1_, DECS);
        transpose_h_kernel<<<dim3((H1_+31)/32, (H1_+31)/32),  tb>>>(W1, wT+WT_W1, H1_, H1_, H1_);
        transpose_h_kernel<<<dim3((H1_+31)/32, (H1_+31)/32),  tb>>>(W2, wT+WT_W2, H1_, H1_, H1_);
        transpose_h_kernel<<<dim3((OUT_+31)/32, (H1_+31)/32), tb>>>(Wo, wT+WT_WO, H1_, OUT_, H1_);
    }
    {
        const int n = B_ * HS;
        zero_hc_kernel<<<(n + 255) / 256, 256>>>(h0, c);
    }

    const dim3 grS((G_ + 127) / 128, B_ / 128);   // (12, 256)
    __half* hc = h0;
    __half* hn = h1;

    // encoder
    for (int t = 0; t < T_; t++) {
        lstm_step<0><<<grS, 256, DSMEM>>>(hc, xe + t * XS, wfe, bpe,
                                          hn, c, (__half*)nullptr, 0);
        __half* tmp = hc; hc = hn; hn = tmp;
    }
    // decoder
    for (int t = 0; t < T_; t++) {
        lstm_step<1><<<grS, 256, DSMEM>>>(hc, xd + t * XS, wfd, bpd,
                                          hn, c, dec, t * U_);
        __half* tmp = hc; hc = hn; hn = tmp;
    }

    // dense head
    const dim3 grH((H1_ + 127) / 128, B_ / 128);
    const dim3 grO((OUT_ + 127) / 128, B_ / 128);
    hgemm<1, __half><<<grH, 256, DSMEM>>>(dec, DECS, wT + WT_MAP, DECS,
                                          t1, H1_, bmap, H1_, DECS);
    hgemm<2, __half><<<grH, 256, DSMEM>>>(t1, H1_, wT + WT_W1, H1_,
                                          t2, H1_, b1, H1_, H1_);
    hgemm<2, __half><<<grH, 256, DSMEM>>>(t2, H1_, wT + WT_W2, H1_,
                                          t1, H1_, b2, H1_, H1_);
    hgemm<0, float><<<grO, 256, DSMEM>>>(t1, H1_, wT + WT_WO, H1_,
                                         out, OUT_, bo, OUT_, H1_);
}

// round 8
// speedup vs baseline: 2.0259x; 1.0395x over previous
#include <cuda_runtime.h>
#include <cuda_fp16.h>
#include <math.h>
#include <stdint.h>

// ---------------- problem constants ----------------
#define B_   32768
#define T_   7
#define EIN  60
#define DIN  36
#define U_   356
#define G_   1424          // 4*U
#define H1_  768
#define OUT_ 168
#define HS   360           // padded h width (halves, mult of 8)
#define XS   64            // padded x width
#define KAP  448           // fused K padded (mult of 32)
#define DECS 2496          // padded dec row
#define NCKS (KAP / 32)    // 14 chunks per LSTM step

// ---------------- scratch (device globals) ----------------------------
__device__ __align__(16) __half g_h0 [(size_t)B_ * HS];
__device__ __align__(16) __half g_h1 [(size_t)B_ * HS];
__device__ __align__(16) float  g_c  [(size_t)B_ * U_];
__device__ __align__(16) __half g_dec[(size_t)B_ * DECS];
__device__ __align__(16) __half g_t1 [(size_t)B_ * H1_];
__device__ __align__(16) __half g_t2 [(size_t)B_ * H1_];
__device__ __align__(16) __half g_xe [(size_t)B_ * T_ * XS];
__device__ __align__(16) __half g_xd [(size_t)B_ * T_ * XS];
__device__ __align__(16) __half g_wfe[(size_t)G_ * KAP];
__device__ __align__(16) __half g_wfd[(size_t)G_ * KAP];
__device__ __align__(16) float  g_bpe[G_];
__device__ __align__(16) float  g_bpd[G_];
#define WT_MAP  0
#define WT_W1   (WT_MAP + 768*DECS)
#define WT_W2   (WT_W1  + 768*768)
#define WT_WO   (WT_W2  + 768*768)
#define WT_TOTAL (WT_WO + 168*768)
__device__ __align__(16) __half g_wT[WT_TOTAL];

// ==================== helpers ====================
__device__ __forceinline__ uint32_t smem_u32(const void* p) {
    uint32_t a;
    asm("{ .reg .u64 t; cvta.to.shared.u64 t, %1; cvt.u32.u64 %0, t; }"
        : "=r"(a) : "l"(p));
    return a;
}
__device__ __forceinline__ void cpa16(uint32_t dst, const void* src, uint32_t sz) {
    asm volatile("cp.async.cg.shared.global [%0], [%1], 16, %2;"
                 :: "r"(dst), "l"(src), "r"(sz));
}
__device__ __forceinline__ void cpa_commit() {
    asm volatile("cp.async.commit_group;" ::: "memory");
}
__device__ __forceinline__ void cpa_wait(int ahead) {
    if (ahead >= 2)      asm volatile("cp.async.wait_group 2;" ::: "memory");
    else if (ahead == 1) asm volatile("cp.async.wait_group 1;" ::: "memory");
    else                 asm volatile("cp.async.wait_group 0;" ::: "memory");
}
#define LDSM_X4(r0, r1, r2, r3, addr)                                          \
    asm volatile("ldmatrix.sync.aligned.m8n8.x4.shared.b16 {%0,%1,%2,%3}, [%4];" \
                 : "=r"(r0), "=r"(r1), "=r"(r2), "=r"(r3) : "r"(addr))
__device__ __forceinline__ void mma_f16(float c[4],
                                        uint32_t a0, uint32_t a1,
                                        uint32_t a2, uint32_t a3,
                                        uint32_t b0, uint32_t b1)
{
    asm volatile(
        "mma.sync.aligned.m16n8k16.row.col.f32.f16.f16.f32 "
        "{%0,%1,%2,%3}, {%4,%5,%6,%7}, {%8,%9}, {%0,%1,%2,%3};"
        : "+f"(c[0]), "+f"(c[1]), "+f"(c[2]), "+f"(c[3])
        : "r"(a0), "r"(a1), "r"(a2), "r"(a3), "r"(b0), "r"(b1));
}
__device__ __forceinline__ float sigmoidf_(float v) {
    return 1.f / (1.f + expf(-v));
}
__device__ __forceinline__ void store2(__half* p, float x, float y) {
    *reinterpret_cast<__half2*>(p) = __floats2half2_rn(x, y);
}
__device__ __forceinline__ void store2(float* p, float x, float y) {
    *reinterpret_cast<float2*>(p) = make_float2(x, y);
}

// smem tile: 128 rows x 20 words (32 halves used + 8 pad), per operand
#define ROWW   20
#define TILE_W (128 * ROWW)          // words
#define STG_W  (2 * TILE_W)          // A+B per stage, words
#define NSTG   4
#define DSMEM  (NSTG * STG_W * 4)    // 81920 B

// ==================== fused LSTM step (fp16, cp.async, ldmatrix) ==========
template<int WRITE_DEC>
__global__ void __launch_bounds__(256)
lstm_step(const __half* __restrict__ hin,
          const __half* __restrict__ xin,       // + t*XS, stride T_*XS
          const __half* __restrict__ Wf,
          const float* __restrict__ bperm,
          __half* __restrict__ hout, float* __restrict__ cst,
          __half* __restrict__ dec, int dec_off)
{
    extern __shared__ __align__(16) char dynsmem[];
    const uint32_t sb = smem_u32(dynsmem);

    const int tid  = threadIdx.x;
    const int lane = tid & 31;
    const int w    = tid >> 5;
    const int m0   = blockIdx.y * 128;
    const int n0   = blockIdx.x * 128;

    const int wm = (w >> 2) * 64;
    const int wn = (w & 3) * 32;
    const int g  = lane >> 2;
    const int q4 = lane & 3;

    const int rs = tid >> 2;
    const int kq = tid & 3;

    // ldmatrix lane offsets (words, relative to tile base)
    const int a_off = (wm + (lane & 15)) * ROWW + (lane >> 4) * 4;
    const int b_off = (wn + (lane >> 4) * 8 + (lane & 7)) * ROWW
                    + ((lane >> 3) & 1) * 4;

    float acc[4][4][4];
#pragma unroll
    for (int i = 0; i < 4; i++)
#pragma unroll
        for (int j = 0; j < 4; j++)
#pragma unroll
            for (int q = 0; q < 4; q++) acc[i][j][q] = 0.f;

    auto issue = [&](int c) {
        const int s  = c & 3;
        const int kh = c * 32 + kq * 8;
        const uint32_t base = sb + (uint32_t)(s * STG_W * 4);
#pragma unroll
        for (int rr = 0; rr < 2; rr++) {
            const int r = rs + rr * 64;
            const uint32_t da = base + (uint32_t)(r * ROWW * 4 + kq * 16);
            const void* asrc;
            uint32_t asz = 16;
            if (kh < HS)            asrc = hin + (size_t)(m0 + r) * HS + kh;
            else if (kh < HS + XS)  asrc = xin + (size_t)(m0 + r) * (T_ * XS) + (kh - HS);
            else { asrc = hin; asz = 0; }
            cpa16(da, asrc, asz);
            const int n = n0 + r;
            const void* bsrc = (n < G_) ? (const void*)(Wf + (size_t)n * KAP + kh)
                                        : (const void*)Wf;
            cpa16(da + TILE_W * 4, bsrc, (n < G_) ? 16u : 0u);
        }
        cpa_commit();
    };

    issue(0); issue(1); issue(2);

    for (int c = 0; c < NCKS; c++) {
        const int last = (NCKS - 1 < c + 2) ? NCKS - 1 : c + 2;
        cpa_wait(last - c);
        __syncthreads();
        if (c + 3 < NCKS) issue(c + 3);

        const uint32_t abase = sb + (uint32_t)(((c & 3) * STG_W) * 4);
        const uint32_t bbase = abase + TILE_W * 4;
#pragma unroll
        for (int kg = 0; kg < 2; kg++) {
            const int kb = kg * 8;
            uint32_t af[4][4], bf[4][2];
#pragma unroll
            for (int mt = 0; mt < 4; mt++)
                LDSM_X4(af[mt][0], af[mt][1], af[mt][2], af[mt][3],
                        abase + (uint32_t)((a_off + mt * 16 * ROWW + kb) * 4));
#pragma unroll
            for (int p = 0; p < 2; p++)
                LDSM_X4(bf[2*p][0], bf[2*p][1], bf[2*p+1][0], bf[2*p+1][1],
                        bbase + (uint32_t)((b_off + p * 16 * ROWW + kb) * 4));
#pragma unroll
            for (int mt = 0; mt < 4; mt++)
#pragma unroll
                for (int nt = 0; nt < 4; nt++)
                    mma_f16(acc[mt][nt],
                            af[mt][0], af[mt][1], af[mt][2], af[mt][3],
                            bf[nt][0], bf[nt][1]);
        }
    }
    __syncthreads();   // protect smem reuse by epilogue overlay

    // ---- epilogue: z -> smem halves -> LSTM cell (unit lane-fast) ----
    float* zs = (float*)dynsmem;
    const int ubase = n0 >> 2;
    const int ul = tid & 31;
    const int rb = tid >> 5;
    const int unit = ubase + ul;
#pragma unroll
    for (int half = 0; half < 2; half++) {
        if ((w >> 2) == half) {
#pragma unroll
            for (int mt = 0; mt < 4; mt++) {
#pragma unroll
                for (int nt = 0; nt < 4; nt++) {
                    const int col = n0 + wn + nt * 8 + 2 * q4;
                    if (col >= G_) continue;
                    const float bx = bperm[col], by = bperm[col + 1];
                    const int cr = wn + nt * 8 + 2 * q4;
                    const int rl = mt * 16 + g;
                    zs[rl * 132 + cr]           = acc[mt][nt][0] + bx;
                    zs[rl * 132 + cr + 1]       = acc[mt][nt][1] + by;
                    zs[(rl + 8) * 132 + cr]     = acc[mt][nt][2] + bx;
                    zs[(rl + 8) * 132 + cr + 1] = acc[mt][nt][3] + by;
                }
            }
        }
        __syncthreads();
        if (unit < U_) {
#pragma unroll
            for (int rr = 0; rr < 8; rr++) {
                const int rl = rr * 8 + rb;
                const int b = m0 + half * 64 + rl;
                const float4 zv =
                    *reinterpret_cast<const float4*>(&zs[rl * 132 + ul * 4]);
                const float iv = sigmoidf_(zv.x);
                const float fv = sigmoidf_(zv.y);
                const float gv = tanhf(zv.z);
                const float ov = sigmoidf_(zv.w);
                const size_t ci = (size_t)b * U_ + unit;
                const float cn = fv * cst[ci] + iv * gv;
                const float hn = ov * tanhf(cn);
                cst[ci] = cn;
                hout[(size_t)b * HS + unit] = __float2half_rn(hn);
                if (WRITE_DEC)
                    dec[(size_t)b * DECS + dec_off + unit] = __float2half_rn(hn);
            }
        }
        __syncthreads();
    }
}

// ==================== fp16 GEMM (head) ====================
template<int ACT, typename TO> // ACT: 0 none, 1 relu, 2 tanh
__global__ void __launch_bounds__(256)
hgemm(const __half* __restrict__ A, int lda,
      const __half* __restrict__ Bt, int ldb,
      TO* __restrict__ C, int ldc,
      const float* __restrict__ bias,
      int N, int K)
{
    extern __shared__ __align__(16) char dynsmem[];
    const uint32_t sb = smem_u32(dynsmem);

    const int tid  = threadIdx.x;
    const int lane = tid & 31;
    const int w    = tid >> 5;
    const int m0   = blockIdx.y * 128;
    const int n0   = blockIdx.x * 128;

    const int wm = (w >> 2) * 64;
    const int wn = (w & 3) * 32;
    const int g  = lane >> 2;
    const int q4 = lane & 3;

    const int rs = tid >> 2;
    const int kq = tid & 3;

    const int a_off = (wm + (lane & 15)) * ROWW + (lane >> 4) * 4;
    const int b_off = (wn + (lane >> 4) * 8 + (lane & 7)) * ROWW
                    + ((lane >> 3) & 1) * 4;

    float acc[4][4][4];
#pragma unroll
    for (int i = 0; i < 4; i++)
#pragma unroll
        for (int j = 0; j < 4; j++)
#pragma unroll
            for (int q = 0; q < 4; q++) acc[i][j][q] = 0.f;

    const int nck = K >> 5;

    auto issue = [&](int c) {
        const int s  = c & 3;
        const int kh = c * 32 + kq * 8;
        const uint32_t base = sb + (uint32_t)(s * STG_W * 4);
#pragma unroll
        for (int rr = 0; rr < 2; rr++) {
            const int r = rs + rr * 64;
            const uint32_t da = base + (uint32_t)(r * ROWW * 4 + kq * 16);
            cpa16(da, A + (size_t)(m0 + r) * lda + kh, 16);
            const int n = n0 + r;
            const void* bsrc = (n < N) ? (const void*)(Bt + (size_t)n * ldb + kh)
                                       : (const void*)Bt;
            cpa16(da + TILE_W * 4, bsrc, (n < N) ? 16u : 0u);
        }
        cpa_commit();
    };

    issue(0); issue(1); issue(2);

    for (int c = 0; c < nck; c++) {
        const int last = (nck - 1 < c + 2) ? nck - 1 : c + 2;
        cpa_wait(last - c);
        __syncthreads();
        if (c + 3 < nck) issue(c + 3);

        const uint32_t abase = sb + (uint32_t)(((c & 3) * STG_W) * 4);
        const uint32_t bbase = abase + TILE_W * 4;
#pragma unroll
        for (int kg = 0; kg < 2; kg++) {
            const int kb = kg * 8;
            uint32_t af[4][4], bf[4][2];
#pragma unroll
            for (int mt = 0; mt < 4; mt++)
                LDSM_X4(af[mt][0], af[mt][1], af[mt][2], af[mt][3],
                        abase + (uint32_t)((a_off + mt * 16 * ROWW + kb) * 4));
#pragma unroll
            for (int p = 0; p < 2; p++)
                LDSM_X4(bf[2*p][0], bf[2*p][1], bf[2*p+1][0], bf[2*p+1][1],
                        bbase + (uint32_t)((b_off + p * 16 * ROWW + kb) * 4));
#pragma unroll
            for (int mt = 0; mt < 4; mt++)
#pragma unroll
                for (int nt = 0; nt < 4; nt++)
                    mma_f16(acc[mt][nt],
                            af[mt][0], af[mt][1], af[mt][2], af[mt][3],
                            bf[nt][0], bf[nt][1]);
        }
    }

#pragma unroll
    for (int mt = 0; mt < 4; mt++) {
#pragma unroll
        for (int nt = 0; nt < 4; nt++) {
            const int col = n0 + wn + nt * 8 + 2 * q4;
            if (col >= N) continue;
            const float bx = bias ? bias[col] : 0.f;
            const float by = bias ? bias[col + 1] : 0.f;
#pragma unroll
            for (int half = 0; half < 2; half++) {
                const int row = m0 + wm + mt * 16 + g + half * 8;
                float vx = acc[mt][nt][half * 2 + 0] + bx;
                float vy = acc[mt][nt][half * 2 + 1] + by;
                if (ACT == 1) { vx = fmaxf(vx, 0.f); vy = fmaxf(vy, 0.f); }
                if (ACT == 2) { vx = tanhf(vx); vy = tanhf(vy); }
                store2(&C[(size_t)row * ldc + col], vx, vy);
            }
        }
    }
}

// ==================== prep kernels ====================
__global__ void cvt_x_kernel(const float* __restrict__ x,
                             __half* __restrict__ xh, int W)
{
    const int i = blockIdx.x * 256 + threadIdx.x;
    if (i >= B_ * T_ * XS) return;
    const int j = i & (XS - 1);
    const int bt = i >> 6;
    xh[i] = (j < W) ? __float2half_rn(x[(size_t)bt * W + j]) : __float2half_rn(0.f);
}

__global__ void build_wf_kernel(const float* __restrict__ R,
                                const float* __restrict__ Kin,
                                const float* __restrict__ bias,
                                __half* __restrict__ wf,
                                float* __restrict__ bp, int Kx)
{
    const int j = blockIdx.y;
    const int k = blockIdx.x * 256 + threadIdx.x;
    if (k >= KAP) return;
    const int oj = (j & 3) * U_ + (j >> 2);
    float v = 0.f;
    if (k < U_)                      v = R[(size_t)k * G_ + oj];
    else if (k >= HS && k < HS + Kx) v = Kin[(size_t)(k - HS) * G_ + oj];
    wf[(size_t)j * KAP + k] = __float2half_rn(v);
    if (k == 0) bp[j] = bias[oj];
}

__global__ void transpose_h_kernel(const float* __restrict__ in,
                                   __half* __restrict__ out,
                                   int R, int Cc, int ldo)
{
    __shared__ float t[32][33];
    const int c0 = blockIdx.x * 32, r0 = blockIdx.y * 32;
    const int x = threadIdx.x, y = threadIdx.y;
#pragma unroll
    for (int dy = 0; dy < 32; dy += 8) {
        const int r = r0 + y + dy, c = c0 + x;
        t[y + dy][x] = (r < R && c < Cc) ? in[(size_t)r * Cc + c] : 0.f;
    }
    __syncthreads();
#pragma unroll
    for (int dy = 0; dy < 32; dy += 8) {
        const int r = c0 + y + dy, c = r0 + x;
        if (r < Cc && c < ldo)
            out[(size_t)r * ldo + c] = __float2half_rn(c < R ? t[x][y + dy] : 0.f);
    }
}

__global__ void zero_hc_kernel(__half* h, float* c)
{
    const int i = blockIdx.x * 256 + threadIdx.x;
    if (i < B_ * HS) h[i] = __float2half_rn(0.f);
    if (i < B_ * U_) c[i] = 0.f;
}

// ==================== host orchestration ====================
extern "C" void kernel_launch(void* const* d_in, const int* in_sizes, int n_in,
                              void* d_out, int out_size)
{
    const float* x    = (const float*)d_in[0];
    const float* m    = (const float*)d_in[1];
    const float* encK = (const float*)d_in[2];
    const float* encR = (const float*)d_in[3];
    const float* encB = (const float*)d_in[4];
    const float* decK = (const float*)d_in[5];
    const float* decR = (const float*)d_in[6];
    const float* decB = (const float*)d_in[7];
    const float* Wmap = (const float*)d_in[8];
    const float* bmap = (const float*)d_in[9];
    const float* W1   = (const float*)d_in[10];
    const float* b1   = (const float*)d_in[11];
    const float* W2   = (const float*)d_in[12];
    const float* b2   = (const float*)d_in[13];
    const float* Wo   = (const float*)d_in[14];
    const float* bo   = (const float*)d_in[15];
    float* out = (float*)d_out;

    __half *h0, *h1, *dec, *t1, *t2, *xe, *xd, *wfe, *wfd, *wT;
    float *c, *bpe, *bpd;
    cudaGetSymbolAddress((void**)&h0,  g_h0);
    cudaGetSymbolAddress((void**)&h1,  g_h1);
    cudaGetSymbolAddress((void**)&c,   g_c);
    cudaGetSymbolAddress((void**)&dec, g_dec);
    cudaGetSymbolAddress((void**)&t1,  g_t1);
    cudaGetSymbolAddress((void**)&t2,  g_t2);
    cudaGetSymbolAddress((void**)&xe,  g_xe);
    cudaGetSymbolAddress((void**)&xd,  g_xd);
    cudaGetSymbolAddress((void**)&wfe, g_wfe);
    cudaGetSymbolAddress((void**)&wfd, g_wfd);
    cudaGetSymbolAddress((void**)&bpe, g_bpe);
    cudaGetSymbolAddress((void**)&bpd, g_bpd);
    cudaGetSymbolAddress((void**)&wT,  g_wT);

    cudaFuncSetAttribute(lstm_step<0>, cudaFuncAttributeMaxDynamicSharedMemorySize, DSMEM);
    cudaFuncSetAttribute(lstm_step<1>, cudaFuncAttributeMaxDynamicSharedMemorySize, DSMEM);
    cudaFuncSetAttribute(hgemm<1, __half>, cudaFuncAttributeMaxDynamicSharedMemorySize, DSMEM);
    cudaFuncSetAttribute(hgemm<2, __half>, cudaFuncAttributeMaxDynamicSharedMemorySize, DSMEM);
    cudaFuncSetAttribute(hgemm<0, float>,  cudaFuncAttributeMaxDynamicSharedMemorySize, DSMEM);

    // ---- prep ----
    {
        const int nx = B_ * T_ * XS;
        cvt_x_kernel<<<(nx + 255) / 256, 256>>>(x, xe, EIN);
        cvt_x_kernel<<<(nx + 255) / 256, 256>>>(m, xd, DIN);
    }
    build_wf_kernel<<<dim3((KAP + 255) / 256, G_), 256>>>(encR, encK, encB, wfe, bpe, EIN);
    build_wf_kernel<<<dim3((KAP + 255) / 256, G_), 256>>>(decR, decK, decB, wfd, bpd, DIN);
    {
        dim3 tb(32, 8);
        transpose_h_kernel<<<dim3((H1_+31)/32, (DECS+31)/32), tb>>>(Wmap, wT+WT_MAP, T_*U_, H1_, DECS);
        transpose_h_kernel<<<dim3((H1_+31)/32, (H1_+31)/32),  tb>>>(W1, wT+WT_W1, H1_, H1_, H1_);
        transpose_h_kernel<<<dim3((H1_+31)/32, (H1_+31)/32),  tb>>>(W2, wT+WT_W2, H1_, H1_, H1_);
        transpose_h_kernel<<<dim3((OUT_+31)/32, (H1_+31)/32), tb>>>(Wo, wT+WT_WO, H1_, OUT_, H1_);
    }
    {
        const int n = B_ * HS;
        zero_hc_kernel<<<(n + 255) / 256, 256>>>(h0, c);
    }

    const dim3 grS((G_ + 127) / 128, B_ / 128);   // (12, 256)
    __half* hc = h0;
    __half* hn = h1;

    // encoder
    for (int t = 0; t < T_; t++) {
        lstm_step<0><<<grS, 256, DSMEM>>>(hc, xe + t * XS, wfe, bpe,
                                          hn, c, (__half*)nullptr, 0);
        __half* tmp = hc; hc = hn; hn = tmp;
    }
    // decoder
    for (int t = 0; t < T_; t++) {
        lstm_step<1><<<grS, 256, DSMEM>>>(hc, xd + t * XS, wfd, bpd,
                                          hn, c, dec, t * U_);
        __half* tmp = hc; hc = hn; hn = tmp;
    }

    // dense head
    const dim3 grH((H1_ + 127) / 128, B_ / 128);
    const dim3 grO((OUT_ + 127) / 128, B_ / 128);
    hgemm<1, __half><<<grH, 256, DSMEM>>>(dec, DECS, wT + WT_MAP, DECS,
                                          t1, H1_, bmap, H1_, DECS);
    hgemm<2, __half><<<grH, 256, DSMEM>>>(t1, H1_, wT + WT_W1, H1_,
                                          t2, H1_, b1, H1_, H1_);
    hgemm<2, __half><<<grH, 256, DSMEM>>>(t2, H1_, wT + WT_W2, H1_,
                                          t1, H1_, b2, H1_, H1_);
    hgemm<0, float><<<grO, 256, DSMEM>>>(t1, H1_, wT + WT_WO, H1_,
                                         out, OUT_, bo, OUT_, H1_);
}

// round 9
// speedup vs baseline: 2.3014x; 1.1360x over previous
#include <cuda_runtime.h>
#include <cuda_fp16.h>
#include <math.h>
#include <stdint.h>

// ---------------- problem constants ----------------
#define B_   32768
#define T_   7
#define EIN  60
#define DIN  36
#define U_   356
#define G_   1424          // 4*U
#define H1_  768
#define OUT_ 168
#define HS   360           // padded h width (halves, mult of 8)
#define XS   64            // padded x width
#define KAP  448           // fused K padded (mult of 32)
#define DECS 2496          // padded dec row
#define NCKS (KAP / 32)    // 14 chunks per LSTM step

// ---------------- scratch (device globals) ----------------------------
__device__ __align__(16) __half g_h0 [(size_t)B_ * HS];
__device__ __align__(16) __half g_h1 [(size_t)B_ * HS];
__device__ __align__(16) float  g_c  [(size_t)B_ * U_];
__device__ __align__(16) __half g_dec[(size_t)B_ * DECS];
__device__ __align__(16) __half g_t1 [(size_t)B_ * H1_];
__device__ __align__(16) __half g_t2 [(size_t)B_ * H1_];
__device__ __align__(16) __half g_xe [(size_t)B_ * T_ * XS];
__device__ __align__(16) __half g_xd [(size_t)B_ * T_ * XS];
__device__ __align__(16) __half g_wfe[(size_t)G_ * KAP];
__device__ __align__(16) __half g_wfd[(size_t)G_ * KAP];
__device__ __align__(16) float  g_bpe[G_];
__device__ __align__(16) float  g_bpd[G_];
#define WT_MAP  0
#define WT_W1   (WT_MAP + 768*DECS)
#define WT_W2   (WT_W1  + 768*768)
#define WT_WO   (WT_W2  + 768*768)
#define WT_TOTAL (WT_WO + 168*768)
__device__ __align__(16) __half g_wT[WT_TOTAL];

// ==================== helpers ====================
__device__ __forceinline__ uint32_t smem_u32(const void* p) {
    uint32_t a;
    asm("{ .reg .u64 t; cvta.to.shared.u64 t, %1; cvt.u32.u64 %0, t; }"
        : "=r"(a) : "l"(p));
    return a;
}
__device__ __forceinline__ void cpa16(uint32_t dst, const void* src, uint32_t sz) {
    asm volatile("cp.async.cg.shared.global [%0], [%1], 16, %2;"
                 :: "r"(dst), "l"(src), "r"(sz));
}
__device__ __forceinline__ void cpa_commit() {
    asm volatile("cp.async.commit_group;" ::: "memory");
}
__device__ __forceinline__ void cpa_wait(int ahead) {
    if (ahead >= 2)      asm volatile("cp.async.wait_group 2;" ::: "memory");
    else if (ahead == 1) asm volatile("cp.async.wait_group 1;" ::: "memory");
    else                 asm volatile("cp.async.wait_group 0;" ::: "memory");
}
#define LDSM_X4(r0, r1, r2, r3, addr)                                          \
    asm volatile("ldmatrix.sync.aligned.m8n8.x4.shared.b16 {%0,%1,%2,%3}, [%4];" \
                 : "=r"(r0), "=r"(r1), "=r"(r2), "=r"(r3) : "r"(addr))
__device__ __forceinline__ void mma_f16(float c[4],
                                        uint32_t a0, uint32_t a1,
                                        uint32_t a2, uint32_t a3,
                                        uint32_t b0, uint32_t b1)
{
    asm volatile(
        "mma.sync.aligned.m16n8k16.row.col.f32.f16.f16.f32 "
        "{%0,%1,%2,%3}, {%4,%5,%6,%7}, {%8,%9}, {%0,%1,%2,%3};"
        : "+f"(c[0]), "+f"(c[1]), "+f"(c[2]), "+f"(c[3])
        : "r"(a0), "r"(a1), "r"(a2), "r"(a3), "r"(b0), "r"(b1));
}
// HW tanh (sm_75+): single MUFU op, max abs err ~1.4e-5
__device__ __forceinline__ float htanh(float v) {
    float r;
    asm("tanh.approx.f32 %0, %1;" : "=f"(r) : "f"(v));
    return r;
}
// sigmoid(x) = 0.5*tanh(x/2) + 0.5  (1 MUFU + 2 FMA)
__device__ __forceinline__ float hsig(float v) {
    return fmaf(htanh(v * 0.5f), 0.5f, 0.5f);
}
__device__ __forceinline__ void store2(__half* p, float x, float y) {
    *reinterpret_cast<__half2*>(p) = __floats2half2_rn(x, y);
}
__device__ __forceinline__ void store2(float* p, float x, float y) {
    *reinterpret_cast<float2*>(p) = make_float2(x, y);
}

// smem tile: 128 rows x 20 words (32 halves used + 8 pad), per operand
#define ROWW   20
#define TILE_W (128 * ROWW)          // words
#define STG_W  (2 * TILE_W)          // A+B per stage, words
#define NSTG   4
#define DSMEM  (NSTG * STG_W * 4)    // 81920 B

// ==================== fused LSTM step (fp16, cp.async, ldmatrix) ==========
template<int WRITE_DEC>
__global__ void __launch_bounds__(256)
lstm_step(const __half* __restrict__ hin,
          const __half* __restrict__ xin,       // + t*XS, stride T_*XS
          const __half* __restrict__ Wf,
          const float* __restrict__ bperm,
          __half* __restrict__ hout, float* __restrict__ cst,
          __half* __restrict__ dec, int dec_off)
{
    extern __shared__ __align__(16) char dynsmem[];
    const uint32_t sb = smem_u32(dynsmem);

    const int tid  = threadIdx.x;
    const int lane = tid & 31;
    const int w    = tid >> 5;
    const int m0   = blockIdx.y * 128;
    const int n0   = blockIdx.x * 128;

    const int wm = (w >> 2) * 64;
    const int wn = (w & 3) * 32;
    const int g  = lane >> 2;
    const int q4 = lane & 3;

    const int rs = tid >> 2;
    const int kq = tid & 3;

    const int a_off = (wm + (lane & 15)) * ROWW + (lane >> 4) * 4;
    const int b_off = (wn + (lane >> 4) * 8 + (lane & 7)) * ROWW
                    + ((lane >> 3) & 1) * 4;

    float acc[4][4][4];
#pragma unroll
    for (int i = 0; i < 4; i++)
#pragma unroll
        for (int j = 0; j < 4; j++)
#pragma unroll
            for (int q = 0; q < 4; q++) acc[i][j][q] = 0.f;

    auto issue = [&](int c) {
        const int s  = c & 3;
        const int kh = c * 32 + kq * 8;
        const uint32_t base = sb + (uint32_t)(s * STG_W * 4);
#pragma unroll
        for (int rr = 0; rr < 2; rr++) {
            const int r = rs + rr * 64;
            const uint32_t da = base + (uint32_t)(r * ROWW * 4 + kq * 16);
            const void* asrc;
            uint32_t asz = 16;
            if (kh < HS)            asrc = hin + (size_t)(m0 + r) * HS + kh;
            else if (kh < HS + XS)  asrc = xin + (size_t)(m0 + r) * (T_ * XS) + (kh - HS);
            else { asrc = hin; asz = 0; }
            cpa16(da, asrc, asz);
            const int n = n0 + r;
            const void* bsrc = (n < G_) ? (const void*)(Wf + (size_t)n * KAP + kh)
                                        : (const void*)Wf;
            cpa16(da + TILE_W * 4, bsrc, (n < G_) ? 16u : 0u);
        }
        cpa_commit();
    };

    issue(0); issue(1); issue(2);

    for (int c = 0; c < NCKS; c++) {
        const int last = (NCKS - 1 < c + 2) ? NCKS - 1 : c + 2;
        cpa_wait(last - c);
        __syncthreads();
        if (c + 3 < NCKS) issue(c + 3);

        const uint32_t abase = sb + (uint32_t)(((c & 3) * STG_W) * 4);
        const uint32_t bbase = abase + TILE_W * 4;
#pragma unroll
        for (int kg = 0; kg < 2; kg++) {
            const int kb = kg * 8;
            uint32_t af[4][4], bf[4][2];
#pragma unroll
            for (int mt = 0; mt < 4; mt++)
                LDSM_X4(af[mt][0], af[mt][1], af[mt][2], af[mt][3],
                        abase + (uint32_t)((a_off + mt * 16 * ROWW + kb) * 4));
#pragma unroll
            for (int p = 0; p < 2; p++)
                LDSM_X4(bf[2*p][0], bf[2*p][1], bf[2*p+1][0], bf[2*p+1][1],
                        bbase + (uint32_t)((b_off + p * 16 * ROWW + kb) * 4));
#pragma unroll
            for (int mt = 0; mt < 4; mt++)
#pragma unroll
                for (int nt = 0; nt < 4; nt++)
                    mma_f16(acc[mt][nt],
                            af[mt][0], af[mt][1], af[mt][2], af[mt][3],
                            bf[nt][0], bf[nt][1]);
        }
    }
    __syncthreads();   // protect smem reuse by epilogue overlay

    // ---- epilogue: z -> smem halves -> LSTM cell (unit lane-fast) ----
    float* zs = (float*)dynsmem;
    const int ubase = n0 >> 2;
    const int ul = tid & 31;
    const int rb = tid >> 5;
    const int unit = ubase + ul;
#pragma unroll
    for (int half = 0; half < 2; half++) {
        if ((w >> 2) == half) {
#pragma unroll
            for (int mt = 0; mt < 4; mt++) {
#pragma unroll
                for (int nt = 0; nt < 4; nt++) {
                    const int col = n0 + wn + nt * 8 + 2 * q4;
                    if (col >= G_) continue;
                    const float bx = bperm[col], by = bperm[col + 1];
                    const int cr = wn + nt * 8 + 2 * q4;
                    const int rl = mt * 16 + g;
                    zs[rl * 132 + cr]           = acc[mt][nt][0] + bx;
                    zs[rl * 132 + cr + 1]       = acc[mt][nt][1] + by;
                    zs[(rl + 8) * 132 + cr]     = acc[mt][nt][2] + bx;
                    zs[(rl + 8) * 132 + cr + 1] = acc[mt][nt][3] + by;
                }
            }
        }
        __syncthreads();
        if (unit < U_) {
#pragma unroll
            for (int rr = 0; rr < 8; rr++) {
                const int rl = rr * 8 + rb;
                const int b = m0 + half * 64 + rl;
                const float4 zv =
                    *reinterpret_cast<const float4*>(&zs[rl * 132 + ul * 4]);
                const float iv = hsig(zv.x);
                const float fv = hsig(zv.y);
                const float gv = htanh(zv.z);
                const float ov = hsig(zv.w);
                const size_t ci = (size_t)b * U_ + unit;
                const float cn = fv * cst[ci] + iv * gv;
                const float hn = ov * htanh(cn);
                cst[ci] = cn;
                hout[(size_t)b * HS + unit] = __float2half_rn(hn);
                if (WRITE_DEC)
                    dec[(size_t)b * DECS + dec_off + unit] = __float2half_rn(hn);
            }
        }
        __syncthreads();
    }
}

// ==================== fp16 GEMM (head) ====================
template<int ACT, typename TO> // ACT: 0 none, 1 relu, 2 tanh
__global__ void __launch_bounds__(256)
hgemm(const __half* __restrict__ A, int lda,
      const __half* __restrict__ Bt, int ldb,
      TO* __restrict__ C, int ldc,
      const float* __restrict__ bias,
      int N, int K)
{
    extern __shared__ __align__(16) char dynsmem[];
    const uint32_t sb = smem_u32(dynsmem);

    const int tid  = threadIdx.x;
    const int lane = tid & 31;
    const int w    = tid >> 5;
    const int m0   = blockIdx.y * 128;
    const int n0   = blockIdx.x * 128;

    const int wm = (w >> 2) * 64;
    const int wn = (w & 3) * 32;
    const int g  = lane >> 2;
    const int q4 = lane & 3;

    const int rs = tid >> 2;
    const int kq = tid & 3;

    const int a_off = (wm + (lane & 15)) * ROWW + (lane >> 4) * 4;
    const int b_off = (wn + (lane >> 4) * 8 + (lane & 7)) * ROWW
                    + ((lane >> 3) & 1) * 4;

    float acc[4][4][4];
#pragma unroll
    for (int i = 0; i < 4; i++)
#pragma unroll
        for (int j = 0; j < 4; j++)
#pragma unroll
            for (int q = 0; q < 4; q++) acc[i][j][q] = 0.f;

    const int nck = K >> 5;

    auto issue = [&](int c) {
        const int s  = c & 3;
        const int kh = c * 32 + kq * 8;
        const uint32_t base = sb + (uint32_t)(s * STG_W * 4);
#pragma unroll
        for (int rr = 0; rr < 2; rr++) {
            const int r = rs + rr * 64;
            const uint32_t da = base + (uint32_t)(r * ROWW * 4 + kq * 16);
            cpa16(da, A + (size_t)(m0 + r) * lda + kh, 16);
            const int n = n0 + r;
            const void* bsrc = (n < N) ? (const void*)(Bt + (size_t)n * ldb + kh)
                                       : (const void*)Bt;
            cpa16(da + TILE_W * 4, bsrc, (n < N) ? 16u : 0u);
        }
        cpa_commit();
    };

    issue(0); issue(1); issue(2);

    for (int c = 0; c < nck; c++) {
        const int last = (nck - 1 < c + 2) ? nck - 1 : c + 2;
        cpa_wait(last - c);
        __syncthreads();
        if (c + 3 < nck) issue(c + 3);

        const uint32_t abase = sb + (uint32_t)(((c & 3) * STG_W) * 4);
        const uint32_t bbase = abase + TILE_W * 4;
#pragma unroll
        for (int kg = 0; kg < 2; kg++) {
            const int kb = kg * 8;
            uint32_t af[4][4], bf[4][2];
#pragma unroll
            for (int mt = 0; mt < 4; mt++)
                LDSM_X4(af[mt][0], af[mt][1], af[mt][2], af[mt][3],
                        abase + (uint32_t)((a_off + mt * 16 * ROWW + kb) * 4));
#pragma unroll
            for (int p = 0; p < 2; p++)
                LDSM_X4(bf[2*p][0], bf[2*p][1], bf[2*p+1][0], bf[2*p+1][1],
                        bbase + (uint32_t)((b_off + p * 16 * ROWW + kb) * 4));
#pragma unroll
            for (int mt = 0; mt < 4; mt++)
#pragma unroll
                for (int nt = 0; nt < 4; nt++)
                    mma_f16(acc[mt][nt],
                            af[mt][0], af[mt][1], af[mt][2], af[mt][3],
                            bf[nt][0], bf[nt][1]);
        }
    }

#pragma unroll
    for (int mt = 0; mt < 4; mt++) {
#pragma unroll
        for (int nt = 0; nt < 4; nt++) {
            const int col = n0 + wn + nt * 8 + 2 * q4;
            if (col >= N) continue;
            const float bx = bias ? bias[col] : 0.f;
            const float by = bias ? bias[col + 1] : 0.f;
#pragma unroll
            for (int half = 0; half < 2; half++) {
                const int row = m0 + wm + mt * 16 + g + half * 8;
                float vx = acc[mt][nt][half * 2 + 0] + bx;
                float vy = acc[mt][nt][half * 2 + 1] + by;
                if (ACT == 1) { vx = fmaxf(vx, 0.f); vy = fmaxf(vy, 0.f); }
                if (ACT == 2) { vx = htanh(vx); vy = htanh(vy); }
                store2(&C[(size_t)row * ldc + col], vx, vy);
            }
        }
    }
}

// ==================== prep kernels ====================
__global__ void cvt_x_kernel(const float* __restrict__ x,
                             __half* __restrict__ xh, int W)
{
    const int i = blockIdx.x * 256 + threadIdx.x;
    if (i >= B_ * T_ * XS) return;
    const int j = i & (XS - 1);
    const int bt = i >> 6;
    xh[i] = (j < W) ? __float2half_rn(x[(size_t)bt * W + j]) : __float2half_rn(0.f);
}

__global__ void build_wf_kernel(const float* __restrict__ R,
                                const float* __restrict__ Kin,
                                const float* __restrict__ bias,
                                __half* __restrict__ wf,
                                float* __restrict__ bp, int Kx)
{
    const int j = blockIdx.y;
    const int k = blockIdx.x * 256 + threadIdx.x;
    if (k >= KAP) return;
    const int oj = (j & 3) * U_ + (j >> 2);
    float v = 0.f;
    if (k < U_)                      v = R[(size_t)k * G_ + oj];
    else if (k >= HS && k < HS + Kx) v = Kin[(size_t)(k - HS) * G_ + oj];
    wf[(size_t)j * KAP + k] = __float2half_rn(v);
    if (k == 0) bp[j] = bias[oj];
}

__global__ void transpose_h_kernel(const float* __restrict__ in,
                                   __half* __restrict__ out,
                                   int R, int Cc, int ldo)
{
    __shared__ float t[32][33];
    const int c0 = blockIdx.x * 32, r0 = blockIdx.y * 32;
    const int x = threadIdx.x, y = threadIdx.y;
#pragma unroll
    for (int dy = 0; dy < 32; dy += 8) {
        const int r = r0 + y + dy, c = c0 + x;
        t[y + dy][x] = (r < R && c < Cc) ? in[(size_t)r * Cc + c] : 0.f;
    }
    __syncthreads();
#pragma unroll
    for (int dy = 0; dy < 32; dy += 8) {
        const int r = c0 + y + dy, c = r0 + x;
        if (r < Cc && c < ldo)
            out[(size_t)r * ldo + c] = __float2half_rn(c < R ? t[x][y + dy] : 0.f);
    }
}

__global__ void zero_hc_kernel(__half* h, float* c)
{
    const int i = blockIdx.x * 256 + threadIdx.x;
    if (i < B_ * HS) h[i] = __float2half_rn(0.f);
    if (i < B_ * U_) c[i] = 0.f;
}

// ==================== host orchestration ====================
extern "C" void kernel_launch(void* const* d_in, const int* in_sizes, int n_in,
                              void* d_out, int out_size)
{
    const float* x    = (const float*)d_in[0];
    const float* m    = (const float*)d_in[1];
    const float* encK = (const float*)d_in[2];
    const float* encR = (const float*)d_in[3];
    const float* encB = (const float*)d_in[4];
    const float* decK = (const float*)d_in[5];
    const float* decR = (const float*)d_in[6];
    const float* decB = (const float*)d_in[7];
    const float* Wmap = (const float*)d_in[8];
    const float* bmap = (const float*)d_in[9];
    const float* W1   = (const float*)d_in[10];
    const float* b1   = (const float*)d_in[11];
    const float* W2   = (const float*)d_in[12];
    const float* b2   = (const float*)d_in[13];
    const float* Wo   = (const float*)d_in[14];
    const float* bo   = (const float*)d_in[15];
    float* out = (float*)d_out;

    __half *h0, *h1, *dec, *t1, *t2, *xe, *xd, *wfe, *wfd, *wT;
    float *c, *bpe, *bpd;
    cudaGetSymbolAddress((void**)&h0,  g_h0);
    cudaGetSymbolAddress((void**)&h1,  g_h1);
    cudaGetSymbolAddress((void**)&c,   g_c);
    cudaGetSymbolAddress((void**)&dec, g_dec);
    cudaGetSymbolAddress((void**)&t1,  g_t1);
    cudaGetSymbolAddress((void**)&t2,  g_t2);
    cudaGetSymbolAddress((void**)&xe,  g_xe);
    cudaGetSymbolAddress((void**)&xd,  g_xd);
    cudaGetSymbolAddress((void**)&wfe, g_wfe);
    cudaGetSymbolAddress((void**)&wfd, g_wfd);
    cudaGetSymbolAddress((void**)&bpe, g_bpe);
    cudaGetSymbolAddress((void**)&bpd, g_bpd);
    cudaGetSymbolAddress((void**)&wT,  g_wT);

    cudaFuncSetAttribute(lstm_step<0>, cudaFuncAttributeMaxDynamicSharedMemorySize, DSMEM);
    cudaFuncSetAttribute(lstm_step<1>, cudaFuncAttributeMaxDynamicSharedMemorySize, DSMEM);
    cudaFuncSetAttribute(hgemm<1, __half>, cudaFuncAttributeMaxDynamicSharedMemorySize, DSMEM);
    cudaFuncSetAttribute(hgemm<2, __half>, cudaFuncAttributeMaxDynamicSharedMemorySize, DSMEM);
    cudaFuncSetAttribute(hgemm<0, float>,  cudaFuncAttributeMaxDynamicSharedMemorySize, DSMEM);

    // ---- prep (launch order chosen so launch #5 = first lstm_step,
    //      which is what ncu -s 5 -c 1 captures) ----
    {
        const int nx = B_ * T_ * XS;
        cvt_x_kernel<<<(nx + 255) / 256, 256>>>(x, xe, EIN);       // 0
        cvt_x_kernel<<<(nx + 255) / 256, 256>>>(m, xd, DIN);       // 1
    }
    build_wf_kernel<<<dim3((KAP + 255) / 256, G_), 256>>>(encR, encK, encB, wfe, bpe, EIN);  // 2
    build_wf_kernel<<<dim3((KAP + 255) / 256, G_), 256>>>(decR, decK, decB, wfd, bpd, DIN);  // 3
    {
        const int n = B_ * HS;
        zero_hc_kernel<<<(n + 255) / 256, 256>>>(h0, c);           // 4
    }

    const dim3 grS((G_ + 127) / 128, B_ / 128);   // (12, 256)
    __half* hc = h0;
    __half* hn = h1;

    // encoder (launch 5 = first lstm_step -> profiled by ncu)
    for (int t = 0; t < T_; t++) {
        lstm_step<0><<<grS, 256, DSMEM>>>(hc, xe + t * XS, wfe, bpe,
                                          hn, c, (__half*)nullptr, 0);
        __half* tmp = hc; hc = hn; hn = tmp;
    }
    // decoder
    for (int t = 0; t < T_; t++) {
        lstm_step<1><<<grS, 256, DSMEM>>>(hc, xd + t * XS, wfd, bpd,
                                          hn, c, dec, t * U_);
        __half* tmp = hc; hc = hn; hn = tmp;
    }

    // head weight transposes (after recurrent loop; before head GEMMs)
    {
        dim3 tb(32, 8);
        transpose_h_kernel<<<dim3((H1_+31)/32, (DECS+31)/32), tb>>>(Wmap, wT+WT_MAP, T_*U_, H1_, DECS);
        transpose_h_kernel<<<dim3((H1_+31)/32, (H1_+31)/32),  tb>>>(W1, wT+WT_W1, H1_, H1_, H1_);
        transpose_h_kernel<<<dim3((H1_+31)/32, (H1_+31)/32),  tb>>>(W2, wT+WT_W2, H1_, H1_, H1_);
        transpose_h_kernel<<<dim3((OUT_+31)/32, (H1_+31)/32), tb>>>(Wo, wT+WT_WO, H1_, OUT_, H1_);
    }

    // dense head
    const dim3 grH((H1_ + 127) / 128, B_ / 128);
    const dim3 grO((OUT_ + 127) / 128, B_ / 128);
    hgemm<1, __half><<<grH, 256, DSMEM>>>(dec, DECS, wT + WT_MAP, DECS,
                                          t1, H1_, bmap, H1_, DECS);
    hgemm<2, __half><<<grH, 256, DSMEM>>>(t1, H1_, wT + WT_W1, H1_,
                                          t2, H1_, b1, H1_, H1_);
    hgemm<2, __half><<<grH, 256, DSMEM>>>(t2, H1_, wT + WT_W2, H1_,
                                          t1, H1_, b2, H1_, H1_);
    hgemm<0, float><<<grO, 256, DSMEM>>>(t1, H1_, wT + WT_WO, H1_,
                                         out, OUT_, bo, OUT_, H1_);
}